// round 1
// baseline (speedup 1.0000x reference)
#include <cuda_runtime.h>
#include <math_constants.h>

#define BB 16
#define HH 16
#define SDIM 512
#define DDIM 64
#define QT 64
#define NKT 8
#define THREADS 256
#define SSTR 520
#define KSTR 65

#define L_ATT 0.33f
#define L_DIST 0.33f
#define L_ADJ (1.0f - 0.33f - 0.33f)

#define SMEM_BYTES ((QT*SSTR + 2*QT*KSTR) * 4)

// Head-independent blend matrix C[b] = 0.33*p_dist + 0.34*adj_norm, 16 MB scratch.
__device__ float g_C[(size_t)BB * SDIM * SDIM];

__global__ __launch_bounds__(256) void precompute_C_kernel(
    const float* __restrict__ adj,
    const float* __restrict__ dist,
    const float* __restrict__ mask)
{
    int row = blockIdx.x;          // b*S + i
    int b = row >> 9;              // / 512
    const float* arow = adj  + (size_t)row * SDIM;
    const float* drow = dist + (size_t)row * SDIM;
    const float* mrow = mask + (size_t)b * SDIM;
    float* crow = g_C + (size_t)row * SDIM;

    int tid = threadIdx.x;
    int w = tid >> 5, l = tid & 31;

    float a0 = arow[tid], a1 = arow[tid + 256];
    float d0 = drow[tid], d1 = drow[tid + 256];
    float m0 = mrow[tid], m1 = mrow[tid + 256];
    float x0 = (m0 == 0.0f) ? -CUDART_INF_F : -d0;
    float x1 = (m1 == 0.0f) ? -CUDART_INF_F : -d1;

    float asum = a0 + a1;
    float xmax = fmaxf(x0, x1);
    #pragma unroll
    for (int o = 16; o > 0; o >>= 1) {
        asum += __shfl_xor_sync(0xffffffffu, asum, o);
        xmax = fmaxf(xmax, __shfl_xor_sync(0xffffffffu, xmax, o));
    }
    __shared__ float rs[8], rm[8], re[8];
    if (l == 0) { rs[w] = asum; rm[w] = xmax; }
    __syncthreads();
    float ts = 0.0f, tm = -CUDART_INF_F;
    #pragma unroll
    for (int i = 0; i < 8; i++) { ts += rs[i]; tm = fmaxf(tm, rm[i]); }

    float e0 = __expf(x0 - tm);
    float e1 = __expf(x1 - tm);
    float es = e0 + e1;
    #pragma unroll
    for (int o = 16; o > 0; o >>= 1)
        es += __shfl_xor_sync(0xffffffffu, es, o);
    if (l == 0) re[w] = es;
    __syncthreads();
    float te = 0.0f;
    #pragma unroll
    for (int i = 0; i < 8; i++) te += re[i];

    float inv_a = 1.0f / (ts + 1e-6f);
    float inv_e = 1.0f / te;
    crow[tid]       = L_DIST * e0 * inv_e + L_ADJ * a0 * inv_a;
    crow[tid + 256] = L_DIST * e1 * inv_e + L_ADJ * a1 * inv_a;
}

__global__ __launch_bounds__(256) void attn_kernel(
    const float* __restrict__ Q, const float* __restrict__ K,
    const float* __restrict__ V, const float* __restrict__ mask,
    float* __restrict__ Og, float* __restrict__ Pg)
{
    extern __shared__ float sm[];
    float* sSc = sm;                     // QT x SSTR  (full score strip)
    float* sQ  = sSc + QT * SSTR;        // QT x KSTR
    float* sKV = sQ  + QT * KSTR;        // QT x KSTR  (K tile, then V tile)

    int qt = blockIdx.x, h = blockIdx.y, b = blockIdx.z;
    int q0 = qt * QT;
    size_t bh = (size_t)b * HH + h;
    const float* Qp = Q + (bh * SDIM + q0) * DDIM;
    const float* Kp = K + bh * SDIM * DDIM;
    const float* Vp = V + bh * SDIM * DDIM;
    const float* Mp = mask + (size_t)b * SDIM;
    const float* Cp = g_C + ((size_t)b * SDIM + q0) * SDIM;
    float* Op = Og + (bh * SDIM + q0) * DDIM;
    float* Pp = Pg + (bh * SDIM + q0) * SDIM;

    int tid = threadIdx.x;
    int tx = tid & 15, ty = tid >> 4;

    // Load Q tile (64x64), coalesced
    for (int i = tid; i < QT * DDIM; i += THREADS)
        sQ[(i >> 6) * KSTR + (i & 63)] = Qp[i];

    // ---- S = Q K^T / 8, masked, into smem score strip ----
    for (int kt = 0; kt < NKT; ++kt) {
        __syncthreads();
        for (int i = tid; i < QT * DDIM; i += THREADS)
            sKV[(i >> 6) * KSTR + (i & 63)] = Kp[(size_t)kt * QT * DDIM + i];
        __syncthreads();

        float acc[4][4];
        #pragma unroll
        for (int i = 0; i < 4; i++)
            #pragma unroll
            for (int j = 0; j < 4; j++) acc[i][j] = 0.0f;

        #pragma unroll 4
        for (int d = 0; d < DDIM; ++d) {
            float a[4], bb[4];
            #pragma unroll
            for (int i = 0; i < 4; i++) a[i] = sQ[(ty + 16 * i) * KSTR + d];
            #pragma unroll
            for (int j = 0; j < 4; j++) bb[j] = sKV[(tx + 16 * j) * KSTR + d];
            #pragma unroll
            for (int i = 0; i < 4; i++)
                #pragma unroll
                for (int j = 0; j < 4; j++)
                    acc[i][j] = fmaf(a[i], bb[j], acc[i][j]);
        }
        #pragma unroll
        for (int j = 0; j < 4; j++) {
            int k = kt * QT + tx + 16 * j;
            float mv = Mp[k];
            #pragma unroll
            for (int i = 0; i < 4; i++) {
                float v = (mv == 0.0f) ? -1e12f : acc[i][j] * 0.125f;
                sSc[(ty + 16 * i) * SSTR + k] = v;
            }
        }
    }
    __syncthreads();

    // ---- Row softmax (each warp owns 8 q-rows), write p_attn, blend with C ----
    {
        int w = tid >> 5, l = tid & 31;
        for (int r = 0; r < 8; ++r) {
            int q = w * 8 + r;
            float* srow = sSc + q * SSTR;
            const float* crow = Cp + (size_t)q * SDIM;
            float* prow = Pp + (size_t)q * SDIM;
            float v[16];
            float m = -CUDART_INF_F;
            #pragma unroll
            for (int t = 0; t < 16; t++) {
                v[t] = srow[l + 32 * t];
                m = fmaxf(m, v[t]);
            }
            #pragma unroll
            for (int o = 16; o > 0; o >>= 1)
                m = fmaxf(m, __shfl_xor_sync(0xffffffffu, m, o));
            float sum = 0.0f;
            #pragma unroll
            for (int t = 0; t < 16; t++) { v[t] = __expf(v[t] - m); sum += v[t]; }
            #pragma unroll
            for (int o = 16; o > 0; o >>= 1)
                sum += __shfl_xor_sync(0xffffffffu, sum, o);
            float inv = 1.0f / sum;
            #pragma unroll
            for (int t = 0; t < 16; t++) {
                int k = l + 32 * t;
                float p = v[t] * inv;
                __stcs(prow + k, p);              // streaming: never re-read
                srow[k] = L_ATT * p + crow[k];    // blended weights for PV
            }
        }
    }

    // ---- out = P_blend @ V ----
    float acc[4][4];
    #pragma unroll
    for (int i = 0; i < 4; i++)
        #pragma unroll
        for (int j = 0; j < 4; j++) acc[i][j] = 0.0f;

    for (int kt = 0; kt < NKT; ++kt) {
        __syncthreads();
        for (int i = tid; i < QT * DDIM; i += THREADS)
            sKV[(i >> 6) * KSTR + (i & 63)] = Vp[(size_t)kt * QT * DDIM + i];
        __syncthreads();

        #pragma unroll 2
        for (int k = 0; k < QT; ++k) {
            float a[4], bb[4];
            #pragma unroll
            for (int i = 0; i < 4; i++)
                a[i] = sSc[(ty + 16 * i) * SSTR + kt * QT + k];
            #pragma unroll
            for (int j = 0; j < 4; j++)
                bb[j] = sKV[k * KSTR + tx + 16 * j];
            #pragma unroll
            for (int i = 0; i < 4; i++)
                #pragma unroll
                for (int j = 0; j < 4; j++)
                    acc[i][j] = fmaf(a[i], bb[j], acc[i][j]);
        }
    }
    #pragma unroll
    for (int i = 0; i < 4; i++)
        #pragma unroll
        for (int j = 0; j < 4; j++)
            Op[(ty + 16 * i) * DDIM + tx + 16 * j] = acc[i][j];
}

extern "C" void kernel_launch(void* const* d_in, const int* in_sizes, int n_in,
                              void* d_out, int out_size)
{
    const float* Q    = (const float*)d_in[0];
    const float* K    = (const float*)d_in[1];
    const float* V    = (const float*)d_in[2];
    const float* mask = (const float*)d_in[3];
    const float* adj  = (const float*)d_in[4];
    const float* dist = (const float*)d_in[5];

    float* outp  = (float*)d_out;
    float* pattn = outp + (size_t)BB * HH * SDIM * DDIM;

    precompute_C_kernel<<<BB * SDIM, THREADS>>>(adj, dist, mask);

    cudaFuncSetAttribute(attn_kernel,
                         cudaFuncAttributeMaxDynamicSharedMemorySize, SMEM_BYTES);
    dim3 grid(NKT, HH, BB);
    attn_kernel<<<grid, THREADS, SMEM_BYTES>>>(Q, K, V, mask, outp, pattn);
}

// round 3
// speedup vs baseline: 3.3615x; 3.3615x over previous
#include <cuda_runtime.h>
#include <cuda_bf16.h>
#include <math_constants.h>
#include <cstdint>

#define BB 16
#define HH 16
#define SDIM 512
#define DDIM 64
#define QT 64
#define NKT 8
#define THREADS 256
#define SSTR 520
#define KSTR 72

#define L_ATT 0.33f
#define L_DIST 0.33f
#define L_ADJ (1.0f - 0.33f - 0.33f)

// smem: strip 64x520 f32 | Qhi | Qlo | Bhi | Blo (64x72 bf16 each) | mask
#define OFF_Q 133120
#define SMEM_BYTES (OFF_Q + 4 * QT * KSTR * 2 + 2048)

__device__ float g_C[(size_t)BB * SDIM * SDIM];

__global__ __launch_bounds__(256) void precompute_C_kernel(
    const float* __restrict__ adj, const float* __restrict__ dist,
    const float* __restrict__ mask)
{
    int row = blockIdx.x;
    int b = row >> 9;
    const float* arow = adj  + (size_t)row * SDIM;
    const float* drow = dist + (size_t)row * SDIM;
    const float* mrow = mask + (size_t)b * SDIM;
    float* crow = g_C + (size_t)row * SDIM;
    int tid = threadIdx.x, w = tid >> 5, l = tid & 31;

    float a0 = arow[tid], a1 = arow[tid + 256];
    float d0 = drow[tid], d1 = drow[tid + 256];
    float m0 = mrow[tid], m1 = mrow[tid + 256];
    float x0 = (m0 == 0.0f) ? -CUDART_INF_F : -d0;
    float x1 = (m1 == 0.0f) ? -CUDART_INF_F : -d1;

    float asum = a0 + a1, xmax = fmaxf(x0, x1);
    #pragma unroll
    for (int o = 16; o > 0; o >>= 1) {
        asum += __shfl_xor_sync(0xffffffffu, asum, o);
        xmax = fmaxf(xmax, __shfl_xor_sync(0xffffffffu, xmax, o));
    }
    __shared__ float rs[8], rm[8], re[8];
    if (l == 0) { rs[w] = asum; rm[w] = xmax; }
    __syncthreads();
    float ts = 0.0f, tm = -CUDART_INF_F;
    #pragma unroll
    for (int i = 0; i < 8; i++) { ts += rs[i]; tm = fmaxf(tm, rm[i]); }

    float e0 = __expf(x0 - tm), e1 = __expf(x1 - tm), es = e0 + e1;
    #pragma unroll
    for (int o = 16; o > 0; o >>= 1) es += __shfl_xor_sync(0xffffffffu, es, o);
    if (l == 0) re[w] = es;
    __syncthreads();
    float te = 0.0f;
    #pragma unroll
    for (int i = 0; i < 8; i++) te += re[i];

    float inv_a = 1.0f / (ts + 1e-6f), inv_e = 1.0f / te;
    crow[tid]       = L_DIST * e0 * inv_e + L_ADJ * a0 * inv_a;
    crow[tid + 256] = L_DIST * e1 * inv_e + L_ADJ * a1 * inv_a;
}

__device__ __forceinline__ void mma_bf16(float* c, const uint32_t* a, const uint32_t* b) {
    asm volatile("mma.sync.aligned.m16n8k16.row.col.f32.bf16.bf16.f32 "
        "{%0,%1,%2,%3}, {%4,%5,%6,%7}, {%8,%9}, {%0,%1,%2,%3};"
        : "+f"(c[0]), "+f"(c[1]), "+f"(c[2]), "+f"(c[3])
        : "r"(a[0]), "r"(a[1]), "r"(a[2]), "r"(a[3]), "r"(b[0]), "r"(b[1]));
}

// pack two f32 -> bf16x2 (lo in bits[15:0])
__device__ __forceinline__ uint32_t packbf(float lo, float hi) {
    uint32_t r;
    asm("cvt.rn.bf16x2.f32 %0, %1, %2;" : "=r"(r) : "f"(hi), "f"(lo));
    return r;
}
__device__ __forceinline__ float bfround(float x) {
    return __bfloat162float(__float2bfloat16_rn(x));
}

__global__ __launch_bounds__(256) void attn_mma_kernel(
    const float* __restrict__ Q, const float* __restrict__ K,
    const float* __restrict__ V, const float* __restrict__ mask,
    float* __restrict__ Og, float* __restrict__ Pg)
{
    extern __shared__ char smem[];
    float* sS = (float*)smem;
    __nv_bfloat16* sQhi = (__nv_bfloat16*)(smem + OFF_Q);
    __nv_bfloat16* sQlo = sQhi + QT * KSTR;
    __nv_bfloat16* sBhi = sQlo + QT * KSTR;   // K tiles, then V^T tiles
    __nv_bfloat16* sBlo = sBhi + QT * KSTR;
    float* sMask = (float*)(smem + OFF_Q + 4 * QT * KSTR * 2);

    int tid = threadIdx.x;
    int wid = tid >> 5, l = tid & 31;
    int wr = wid >> 1, wc = wid & 1;
    int lr = l >> 2, lc = l & 3;

    int qt = blockIdx.x, h = blockIdx.y, b = blockIdx.z;
    int q0 = qt * QT;
    size_t bh = (size_t)b * HH + h;
    const float* Qp = Q + (bh * SDIM + q0) * DDIM;
    const float* Kp = K + bh * SDIM * DDIM;
    const float* Vp = V + bh * SDIM * DDIM;
    const float* Mp = mask + (size_t)b * SDIM;
    const float* Cp = g_C + ((size_t)b * SDIM + q0) * SDIM;
    float* Op = Og + (bh * SDIM + q0) * DDIM;
    float* Pp = Pg + (bh * SDIM + q0) * SDIM;

    for (int i = tid; i < SDIM; i += THREADS) sMask[i] = Mp[i];

    // ---- Load Q (scaled by 1/8), split hi/lo bf16 ----
    {
        const float4* Q4 = (const float4*)Qp;
        #pragma unroll
        for (int t = 0; t < 4; ++t) {
            int idx = tid + 256 * t;
            float4 f = Q4[idx];
            int r = idx >> 4, c = (idx & 15) << 2;
            float v[4] = {f.x * 0.125f, f.y * 0.125f, f.z * 0.125f, f.w * 0.125f};
            #pragma unroll
            for (int e = 0; e < 4; ++e) {
                float hi = bfround(v[e]);
                sQhi[r * KSTR + c + e] = __float2bfloat16_rn(v[e]);
                sQlo[r * KSTR + c + e] = __float2bfloat16_rn(v[e] - hi);
            }
        }
    }

    // ---- Phase 1: scores into strip, 3-pass bf16 mma ----
    float4 pf[4];
    {
        const float4* K4 = (const float4*)Kp;
        #pragma unroll
        for (int t = 0; t < 4; ++t) pf[t] = K4[tid + 256 * t];
    }
    for (int kt = 0; kt < NKT; ++kt) {
        // convert current prefetched K tile into smem
        #pragma unroll
        for (int t = 0; t < 4; ++t) {
            int idx = tid + 256 * t;
            int r = idx >> 4, c = (idx & 15) << 2;
            float v[4] = {pf[t].x, pf[t].y, pf[t].z, pf[t].w};
            #pragma unroll
            for (int e = 0; e < 4; ++e) {
                float hi = bfround(v[e]);
                sBhi[r * KSTR + c + e] = __float2bfloat16_rn(v[e]);
                sBlo[r * KSTR + c + e] = __float2bfloat16_rn(v[e] - hi);
            }
        }
        __syncthreads();
        if (kt < NKT - 1) {
            const float4* K4 = (const float4*)(Kp + (size_t)(kt + 1) * QT * DDIM);
            #pragma unroll
            for (int t = 0; t < 4; ++t) pf[t] = K4[tid + 256 * t];
        }

        float acc[4][4];
        #pragma unroll
        for (int j = 0; j < 4; ++j)
            #pragma unroll
            for (int e = 0; e < 4; ++e) acc[j][e] = 0.0f;

        #pragma unroll
        for (int pass = 0; pass < 3; ++pass) {
            const __nv_bfloat16* Am = (pass == 1) ? sQlo : sQhi;
            const __nv_bfloat16* Bm = (pass == 2) ? sBlo : sBhi;
            #pragma unroll
            for (int ks = 0; ks < 4; ++ks) {
                int ar = 16 * wr + lr;
                int ad = ks * 16 + 2 * lc;
                uint32_t a[4];
                a[0] = *(const uint32_t*)(Am + ar * KSTR + ad);
                a[1] = *(const uint32_t*)(Am + (ar + 8) * KSTR + ad);
                a[2] = *(const uint32_t*)(Am + ar * KSTR + ad + 8);
                a[3] = *(const uint32_t*)(Am + (ar + 8) * KSTR + ad + 8);
                #pragma unroll
                for (int j = 0; j < 4; ++j) {
                    int bn = 32 * wc + 8 * j + lr;
                    uint32_t bfr[2];
                    bfr[0] = *(const uint32_t*)(Bm + bn * KSTR + ad);
                    bfr[1] = *(const uint32_t*)(Bm + bn * KSTR + ad + 8);
                    mma_bf16(acc[j], a, bfr);
                }
            }
        }
        // store score frags to strip
        #pragma unroll
        for (int j = 0; j < 4; ++j) {
            int col = kt * 64 + 32 * wc + 8 * j + 2 * lc;
            int ar = 16 * wr + lr;
            *(float2*)(sS + ar * SSTR + col)       = make_float2(acc[j][0], acc[j][1]);
            *(float2*)(sS + (ar + 8) * SSTR + col) = make_float2(acc[j][2], acc[j][3]);
        }
        __syncthreads();
    }

    // ---- Phase 2: softmax per row, write p_attn, blend with C into strip ----
    for (int rr = 0; rr < 8; ++rr) {
        int q = wid * 8 + rr;
        float v[16];
        #pragma unroll
        for (int t = 0; t < 4; ++t) {
            float4 f = *(float4*)(sS + q * SSTR + l * 4 + 128 * t);
            int c0 = l * 4 + 128 * t;
            v[t*4+0] = (sMask[c0+0] == 0.0f) ? -1e12f : f.x;
            v[t*4+1] = (sMask[c0+1] == 0.0f) ? -1e12f : f.y;
            v[t*4+2] = (sMask[c0+2] == 0.0f) ? -1e12f : f.z;
            v[t*4+3] = (sMask[c0+3] == 0.0f) ? -1e12f : f.w;
        }
        float m = -CUDART_INF_F;
        #pragma unroll
        for (int t = 0; t < 16; ++t) m = fmaxf(m, v[t]);
        #pragma unroll
        for (int o = 16; o > 0; o >>= 1)
            m = fmaxf(m, __shfl_xor_sync(0xffffffffu, m, o));
        float sum = 0.0f;
        #pragma unroll
        for (int t = 0; t < 16; ++t) { v[t] = __expf(v[t] - m); sum += v[t]; }
        #pragma unroll
        for (int o = 16; o > 0; o >>= 1)
            sum += __shfl_xor_sync(0xffffffffu, sum, o);
        float inv = 1.0f / sum;
        const float* Crow = Cp + (size_t)q * SDIM;
        float* Prow = Pp + (size_t)q * SDIM;
        #pragma unroll
        for (int t = 0; t < 4; ++t) {
            int c0 = l * 4 + 128 * t;
            float4 p;
            p.x = v[t*4+0] * inv; p.y = v[t*4+1] * inv;
            p.z = v[t*4+2] * inv; p.w = v[t*4+3] * inv;
            __stcs((float4*)(Prow + c0), p);
            float4 cw = *(const float4*)(Crow + c0);
            float4 wv;
            wv.x = fmaf(L_ATT, p.x, cw.x); wv.y = fmaf(L_ATT, p.y, cw.y);
            wv.z = fmaf(L_ATT, p.z, cw.z); wv.w = fmaf(L_ATT, p.w, cw.w);
            *(float4*)(sS + q * SSTR + c0) = wv;
        }
    }
    __syncthreads();

    // ---- Phase 3: out = W @ V, V transposed hi/lo in smem, 3-pass ----
    float accO[4][4];
    #pragma unroll
    for (int j = 0; j < 4; ++j)
        #pragma unroll
        for (int e = 0; e < 4; ++e) accO[j][e] = 0.0f;

    {
        const float4* V4 = (const float4*)Vp;
        #pragma unroll
        for (int t = 0; t < 4; ++t) {
            int idx = tid + 256 * t;
            pf[t] = V4[(idx & 63) * 16 + (idx >> 6)];
        }
    }
    for (int kt = 0; kt < NKT; ++kt) {
        // transpose-store V tile: sB*[d][k], stride KSTR
        #pragma unroll
        for (int t = 0; t < 4; ++t) {
            int idx = tid + 256 * t;
            int kk = idx & 63, d0 = (idx >> 6) << 2;
            float v[4] = {pf[t].x, pf[t].y, pf[t].z, pf[t].w};
            #pragma unroll
            for (int e = 0; e < 4; ++e) {
                float hi = bfround(v[e]);
                sBhi[(d0 + e) * KSTR + kk] = __float2bfloat16_rn(v[e]);
                sBlo[(d0 + e) * KSTR + kk] = __float2bfloat16_rn(v[e] - hi);
            }
        }
        __syncthreads();
        if (kt < NKT - 1) {
            const float4* V4 = (const float4*)(Vp + (size_t)(kt + 1) * QT * DDIM);
            #pragma unroll
            for (int t = 0; t < 4; ++t) {
                int idx = tid + 256 * t;
                pf[t] = V4[(idx & 63) * 16 + (idx >> 6)];
            }
        }

        #pragma unroll
        for (int ks = 0; ks < 4; ++ks) {
            int kcol = kt * 64 + ks * 16 + 2 * lc;
            int ar = 16 * wr + lr;
            float2 w00 = *(float2*)(sS + ar * SSTR + kcol);
            float2 w10 = *(float2*)(sS + (ar + 8) * SSTR + kcol);
            float2 w01 = *(float2*)(sS + ar * SSTR + kcol + 8);
            float2 w11 = *(float2*)(sS + (ar + 8) * SSTR + kcol + 8);
            uint32_t ahi[4], alo[4];
            ahi[0] = packbf(w00.x, w00.y);
            ahi[1] = packbf(w10.x, w10.y);
            ahi[2] = packbf(w01.x, w01.y);
            ahi[3] = packbf(w11.x, w11.y);
            alo[0] = packbf(w00.x - bfround(w00.x), w00.y - bfround(w00.y));
            alo[1] = packbf(w10.x - bfround(w10.x), w10.y - bfround(w10.y));
            alo[2] = packbf(w01.x - bfround(w01.x), w01.y - bfround(w01.y));
            alo[3] = packbf(w11.x - bfround(w11.x), w11.y - bfround(w11.y));
            int bd = ks * 16 + 2 * lc;
            #pragma unroll
            for (int pass = 0; pass < 3; ++pass) {
                const uint32_t* A = (pass == 1) ? alo : ahi;
                const __nv_bfloat16* Bm = (pass == 2) ? sBlo : sBhi;
                #pragma unroll
                for (int j = 0; j < 4; ++j) {
                    int n = 32 * wc + 8 * j + lr;
                    uint32_t bfr[2];
                    bfr[0] = *(const uint32_t*)(Bm + n * KSTR + bd);
                    bfr[1] = *(const uint32_t*)(Bm + n * KSTR + bd + 8);
                    mma_bf16(accO[j], A, bfr);
                }
            }
        }
        __syncthreads();
    }

    // ---- Write out ----
    #pragma unroll
    for (int j = 0; j < 4; ++j) {
        int col = 32 * wc + 8 * j + 2 * lc;
        int ar = 16 * wr + lr;
        *(float2*)(Op + ar * DDIM + col)       = make_float2(accO[j][0], accO[j][1]);
        *(float2*)(Op + (ar + 8) * DDIM + col) = make_float2(accO[j][2], accO[j][3]);
    }
}

extern "C" void kernel_launch(void* const* d_in, const int* in_sizes, int n_in,
                              void* d_out, int out_size)
{
    const float* Q    = (const float*)d_in[0];
    const float* K    = (const float*)d_in[1];
    const float* V    = (const float*)d_in[2];
    const float* mask = (const float*)d_in[3];
    const float* adj  = (const float*)d_in[4];
    const float* dist = (const float*)d_in[5];

    float* outp  = (float*)d_out;
    float* pattn = outp + (size_t)BB * HH * SDIM * DDIM;

    precompute_C_kernel<<<BB * SDIM, THREADS>>>(adj, dist, mask);

    cudaFuncSetAttribute(attn_mma_kernel,
                         cudaFuncAttributeMaxDynamicSharedMemorySize, SMEM_BYTES);
    dim3 grid(NKT, HH, BB);
    attn_mma_kernel<<<grid, THREADS, SMEM_BYTES>>>(Q, K, V, mask, outp, pattn);
}

// round 4
// speedup vs baseline: 3.5298x; 1.0501x over previous
#include <cuda_runtime.h>
#include <cuda_bf16.h>
#include <math_constants.h>
#include <cstdint>

#define BB 16
#define HH 16
#define SDIM 512
#define DDIM 64
#define QT 64
#define NKT 8
#define THREADS 256
#define SSTRW 524          // f32 words per strip row (524 % 32 = 12 -> conflict-free ldmatrix)
#define WROWB 2096         // strip row bytes
#define KSTRB 144          // bf16 tile row bytes (72 bf16)

#define L_ATT 0.33f
#define L_DIST 0.33f
#define L_ADJ (1.0f - 0.33f - 0.33f)

#define OFF_Q    134144    // 64*2096
#define OFF_QLO  (OFF_Q + 9216)
#define OFF_BHI  (OFF_Q + 18432)
#define OFF_BLO  (OFF_Q + 27648)
#define OFF_MASK (OFF_Q + 36864)
#define SMEM_BYTES (OFF_MASK + 2048)

__device__ float g_C[(size_t)BB * SDIM * SDIM];

__global__ __launch_bounds__(256) void precompute_C_kernel(
    const float* __restrict__ adj, const float* __restrict__ dist,
    const float* __restrict__ mask)
{
    int row = blockIdx.x;
    int b = row >> 9;
    const float* arow = adj  + (size_t)row * SDIM;
    const float* drow = dist + (size_t)row * SDIM;
    const float* mrow = mask + (size_t)b * SDIM;
    float* crow = g_C + (size_t)row * SDIM;
    int tid = threadIdx.x, w = tid >> 5, l = tid & 31;

    float a0 = arow[tid], a1 = arow[tid + 256];
    float d0 = drow[tid], d1 = drow[tid + 256];
    float m0 = mrow[tid], m1 = mrow[tid + 256];
    float x0 = (m0 == 0.0f) ? -CUDART_INF_F : -d0;
    float x1 = (m1 == 0.0f) ? -CUDART_INF_F : -d1;

    float asum = a0 + a1, xmax = fmaxf(x0, x1);
    #pragma unroll
    for (int o = 16; o > 0; o >>= 1) {
        asum += __shfl_xor_sync(0xffffffffu, asum, o);
        xmax = fmaxf(xmax, __shfl_xor_sync(0xffffffffu, xmax, o));
    }
    __shared__ float rs[8], rm[8], re[8];
    if (l == 0) { rs[w] = asum; rm[w] = xmax; }
    __syncthreads();
    float ts = 0.0f, tm = -CUDART_INF_F;
    #pragma unroll
    for (int i = 0; i < 8; i++) { ts += rs[i]; tm = fmaxf(tm, rm[i]); }

    float e0 = __expf(x0 - tm), e1 = __expf(x1 - tm), es = e0 + e1;
    #pragma unroll
    for (int o = 16; o > 0; o >>= 1) es += __shfl_xor_sync(0xffffffffu, es, o);
    if (l == 0) re[w] = es;
    __syncthreads();
    float te = 0.0f;
    #pragma unroll
    for (int i = 0; i < 8; i++) te += re[i];

    float inv_a = 1.0f / (ts + 1e-6f), inv_e = 1.0f / te;
    crow[tid]       = L_DIST * e0 * inv_e + L_ADJ * a0 * inv_a;
    crow[tid + 256] = L_DIST * e1 * inv_e + L_ADJ * a1 * inv_a;
}

__device__ __forceinline__ void mma_bf16(float* c, const uint32_t* a, const uint32_t* b) {
    asm volatile("mma.sync.aligned.m16n8k16.row.col.f32.bf16.bf16.f32 "
        "{%0,%1,%2,%3}, {%4,%5,%6,%7}, {%8,%9}, {%0,%1,%2,%3};"
        : "+f"(c[0]), "+f"(c[1]), "+f"(c[2]), "+f"(c[3])
        : "r"(a[0]), "r"(a[1]), "r"(a[2]), "r"(a[3]), "r"(b[0]), "r"(b[1]));
}
__device__ __forceinline__ void ldm_x4(uint32_t* r, uint32_t a) {
    asm volatile("ldmatrix.sync.aligned.m8n8.x4.shared.b16 {%0,%1,%2,%3}, [%4];"
        : "=r"(r[0]), "=r"(r[1]), "=r"(r[2]), "=r"(r[3]) : "r"(a));
}
__device__ __forceinline__ uint32_t smem_u32(const void* p) {
    uint32_t a;
    asm("{ .reg .u64 t; cvta.to.shared.u64 t, %1; cvt.u32.u64 %0, t; }" : "=r"(a) : "l"(p));
    return a;
}
// pack two f32 -> bf16x2 (first arg in low half)
__device__ __forceinline__ uint32_t packbf(float lo, float hi) {
    uint32_t r;
    asm("cvt.rn.bf16x2.f32 %0, %1, %2;" : "=r"(r) : "f"(hi), "f"(lo));
    return r;
}
__device__ __forceinline__ float bfround(float x) {
    return __bfloat162float(__float2bfloat16_rn(x));
}

__global__ __launch_bounds__(256) void attn_mma_kernel(
    const float* __restrict__ Q, const float* __restrict__ K,
    const float* __restrict__ V, const float* __restrict__ mask,
    float* __restrict__ Og, float* __restrict__ Pg)
{
    extern __shared__ char smem[];
    float* sS = (float*)smem;
    __nv_bfloat16* sQhi = (__nv_bfloat16*)(smem + OFF_Q);
    __nv_bfloat16* sQlo = (__nv_bfloat16*)(smem + OFF_QLO);
    __nv_bfloat16* sBhi = (__nv_bfloat16*)(smem + OFF_BHI);
    __nv_bfloat16* sBlo = (__nv_bfloat16*)(smem + OFF_BLO);
    float* sMask = (float*)(smem + OFF_MASK);
    uint32_t sb = smem_u32(smem);

    int tid = threadIdx.x;
    int wid = tid >> 5, l = tid & 31;
    int wr = wid >> 1, wc = wid & 1;
    int lr = l >> 2, lc = l & 3;
    int lr8 = l & 7, lg = (l >> 3) & 1, kg = l >> 4;

    int qt = blockIdx.x, h = blockIdx.y, b = blockIdx.z;
    int q0 = qt * QT;
    size_t bh_ = (size_t)b * HH + h;
    const float* Qp = Q + (bh_ * SDIM + q0) * DDIM;
    const float* Kp = K + bh_ * SDIM * DDIM;
    const float* Vp = V + bh_ * SDIM * DDIM;
    const float* Mp = mask + (size_t)b * SDIM;
    const float* Cp = g_C + ((size_t)b * SDIM + q0) * SDIM;
    float* Op = Og + (bh_ * SDIM + q0) * DDIM;
    float* Pp = Pg + (bh_ * SDIM + q0) * SDIM;

    for (int i = tid; i < SDIM; i += THREADS) sMask[i] = Mp[i];

    // ---- Load Q (scaled 1/8), split hi/lo bf16, packed stores ----
    {
        const float4* Q4 = (const float4*)Qp;
        #pragma unroll
        for (int t = 0; t < 4; ++t) {
            int idx = tid + 256 * t;
            float4 f = Q4[idx];
            int r = idx >> 4, c = (idx & 15) << 2;
            float v0 = f.x * 0.125f, v1 = f.y * 0.125f, v2 = f.z * 0.125f, v3 = f.w * 0.125f;
            uint32_t h01 = packbf(v0, v1), h23 = packbf(v2, v3);
            uint32_t l01 = packbf(v0 - bfround(v0), v1 - bfround(v1));
            uint32_t l23 = packbf(v2 - bfround(v2), v3 - bfround(v3));
            char* dst = smem + OFF_Q + r * KSTRB + 2 * c;
            *(uint2*)dst = make_uint2(h01, h23);
            *(uint2*)(dst + 9216) = make_uint2(l01, l23);
        }
    }

    // prefetch K tile 0
    float4 pf[4];
    {
        const float4* K4 = (const float4*)Kp;
        #pragma unroll
        for (int t = 0; t < 4; ++t) pf[t] = K4[tid + 256 * t];
    }
    __syncthreads();

    // ---- Resident Q fragments (ldmatrix once) ----
    uint32_t qah[4][4], qal[4][4];
    {
        uint32_t ra = sb + OFF_Q + (16 * wr + lr8 + 8 * lg) * KSTRB + 16 * kg;
        #pragma unroll
        for (int ks = 0; ks < 4; ++ks) {
            ldm_x4(qah[ks], ra + ks * 32);
            ldm_x4(qal[ks], ra + 9216 + ks * 32);
        }
    }

    // ---- Phase 1: scores -> strip ----
    for (int kt = 0; kt < NKT; ++kt) {
        #pragma unroll
        for (int t = 0; t < 4; ++t) {
            int idx = tid + 256 * t;
            int r = idx >> 4, c = (idx & 15) << 2;
            float v0 = pf[t].x, v1 = pf[t].y, v2 = pf[t].z, v3 = pf[t].w;
            uint32_t h01 = packbf(v0, v1), h23 = packbf(v2, v3);
            uint32_t l01 = packbf(v0 - bfround(v0), v1 - bfround(v1));
            uint32_t l23 = packbf(v2 - bfround(v2), v3 - bfround(v3));
            char* dst = smem + OFF_BHI + r * KSTRB + 2 * c;
            *(uint2*)dst = make_uint2(h01, h23);
            *(uint2*)(dst + 9216) = make_uint2(l01, l23);
        }
        __syncthreads();
        if (kt < NKT - 1) {
            const float4* K4 = (const float4*)(Kp + (size_t)(kt + 1) * QT * DDIM);
            #pragma unroll
            for (int t = 0; t < 4; ++t) pf[t] = K4[tid + 256 * t];
        }

        float acc[4][4];
        #pragma unroll
        for (int j = 0; j < 4; ++j)
            #pragma unroll
            for (int e = 0; e < 4; ++e) acc[j][e] = 0.0f;

        #pragma unroll
        for (int ks = 0; ks < 4; ++ks) {
            uint32_t bh[8], bl[8];
            uint32_t rb = sb + OFF_BHI + (32 * wc + lr8 + 8 * kg) * KSTRB + 16 * lg + ks * 32;
            ldm_x4(bh, rb);
            ldm_x4(bh + 4, rb + 16 * KSTRB);
            ldm_x4(bl, rb + 9216);
            ldm_x4(bl + 4, rb + 9216 + 16 * KSTRB);
            #pragma unroll
            for (int j = 0; j < 4; ++j) {
                mma_bf16(acc[j], qah[ks], bh + 2 * j);
                mma_bf16(acc[j], qal[ks], bh + 2 * j);
                mma_bf16(acc[j], qah[ks], bl + 2 * j);
            }
        }
        #pragma unroll
        for (int j = 0; j < 4; ++j) {
            int col = kt * 64 + 32 * wc + 8 * j + 2 * lc;
            int ar = 16 * wr + lr;
            *(float2*)(sS + ar * SSTRW + col)       = make_float2(acc[j][0], acc[j][1]);
            *(float2*)(sS + (ar + 8) * SSTRW + col) = make_float2(acc[j][2], acc[j][3]);
        }
        __syncthreads();
    }

    // ---- Phase 2: softmax, p_attn out, blend -> W (bf16 hi/lo, in-place) ----
    for (int rr = 0; rr < 8; ++rr) {
        int q = wid * 8 + rr;
        float* srow = sS + q * SSTRW;
        float v[16];
        #pragma unroll
        for (int t = 0; t < 4; ++t) {
            float4 f = *(float4*)(srow + l * 4 + 128 * t);
            int c0 = l * 4 + 128 * t;
            v[t*4+0] = (sMask[c0+0] == 0.0f) ? -1e12f : f.x;
            v[t*4+1] = (sMask[c0+1] == 0.0f) ? -1e12f : f.y;
            v[t*4+2] = (sMask[c0+2] == 0.0f) ? -1e12f : f.z;
            v[t*4+3] = (sMask[c0+3] == 0.0f) ? -1e12f : f.w;
        }
        float m = -CUDART_INF_F;
        #pragma unroll
        for (int t = 0; t < 16; ++t) m = fmaxf(m, v[t]);
        #pragma unroll
        for (int o = 16; o > 0; o >>= 1)
            m = fmaxf(m, __shfl_xor_sync(0xffffffffu, m, o));
        float sum = 0.0f;
        #pragma unroll
        for (int t = 0; t < 16; ++t) { v[t] = __expf(v[t] - m); sum += v[t]; }
        #pragma unroll
        for (int o = 16; o > 0; o >>= 1)
            sum += __shfl_xor_sync(0xffffffffu, sum, o);
        float inv = 1.0f / sum;
        __syncwarp();
        const float* Crow = Cp + (size_t)q * SDIM;
        float* Prow = Pp + (size_t)q * SDIM;
        char* Wrow = smem + q * WROWB;
        #pragma unroll
        for (int t = 0; t < 4; ++t) {
            int c0 = l * 4 + 128 * t;
            float4 p;
            p.x = v[t*4+0] * inv; p.y = v[t*4+1] * inv;
            p.z = v[t*4+2] * inv; p.w = v[t*4+3] * inv;
            __stcs((float4*)(Prow + c0), p);
            float4 cw = *(const float4*)(Crow + c0);
            float w0 = fmaf(L_ATT, p.x, cw.x), w1 = fmaf(L_ATT, p.y, cw.y);
            float w2 = fmaf(L_ATT, p.z, cw.z), w3 = fmaf(L_ATT, p.w, cw.w);
            uint32_t h01 = packbf(w0, w1), h23 = packbf(w2, w3);
            uint32_t l01 = packbf(w0 - bfround(w0), w1 - bfround(w1));
            uint32_t l23 = packbf(w2 - bfround(w2), w3 - bfround(w3));
            *(uint2*)(Wrow + 2 * c0)        = make_uint2(h01, h23);
            *(uint2*)(Wrow + 1040 + 2 * c0) = make_uint2(l01, l23);
        }
    }
    __syncthreads();

    // ---- Phase 3: out = W @ V ----
    float accO[4][4];
    #pragma unroll
    for (int j = 0; j < 4; ++j)
        #pragma unroll
        for (int e = 0; e < 4; ++e) accO[j][e] = 0.0f;

    {
        const float4* V4 = (const float4*)Vp;
        #pragma unroll
        for (int t = 0; t < 4; ++t) {
            int idx = tid + 256 * t;
            pf[t] = V4[(idx & 63) * 16 + (idx >> 6)];
        }
    }
    uint32_t wra = sb + (16 * wr + lr8 + 8 * lg) * WROWB + 16 * kg;
    for (int kt = 0; kt < NKT; ++kt) {
        // transpose-store V tile hi/lo: sB[d][k]
        #pragma unroll
        for (int t = 0; t < 4; ++t) {
            int idx = tid + 256 * t;
            int kk = idx & 63, d0 = (idx >> 6) << 2;
            float vv[4] = {pf[t].x, pf[t].y, pf[t].z, pf[t].w};
            #pragma unroll
            for (int e = 0; e < 4; ++e) {
                float hi = bfround(vv[e]);
                sBhi[(d0 + e) * 72 + kk] = __float2bfloat16_rn(vv[e]);
                sBlo[(d0 + e) * 72 + kk] = __float2bfloat16_rn(vv[e] - hi);
            }
        }
        __syncthreads();
        if (kt < NKT - 1) {
            const float4* V4 = (const float4*)(Vp + (size_t)(kt + 1) * QT * DDIM);
            #pragma unroll
            for (int t = 0; t < 4; ++t) {
                int idx = tid + 256 * t;
                pf[t] = V4[(idx & 63) * 16 + (idx >> 6)];
            }
        }

        uint32_t wbase = wra + kt * 128;
        #pragma unroll
        for (int ks = 0; ks < 4; ++ks) {
            uint32_t ah[4], al[4], bh[8], bl[8];
            ldm_x4(ah, wbase + ks * 32);
            ldm_x4(al, wbase + 1040 + ks * 32);
            uint32_t rb = sb + OFF_BHI + (32 * wc + lr8 + 8 * kg) * KSTRB + 16 * lg + ks * 32;
            ldm_x4(bh, rb);
            ldm_x4(bh + 4, rb + 16 * KSTRB);
            ldm_x4(bl, rb + 9216);
            ldm_x4(bl + 4, rb + 9216 + 16 * KSTRB);
            #pragma unroll
            for (int j = 0; j < 4; ++j) {
                mma_bf16(accO[j], ah, bh + 2 * j);
                mma_bf16(accO[j], al, bh + 2 * j);
                mma_bf16(accO[j], ah, bl + 2 * j);
            }
        }
        __syncthreads();
    }

    // ---- Write out ----
    #pragma unroll
    for (int j = 0; j < 4; ++j) {
        int col = 32 * wc + 8 * j + 2 * lc;
        int ar = 16 * wr + lr;
        *(float2*)(Op + ar * DDIM + col)       = make_float2(accO[j][0], accO[j][1]);
        *(float2*)(Op + (ar + 8) * DDIM + col) = make_float2(accO[j][2], accO[j][3]);
    }
}

extern "C" void kernel_launch(void* const* d_in, const int* in_sizes, int n_in,
                              void* d_out, int out_size)
{
    const float* Q    = (const float*)d_in[0];
    const float* K    = (const float*)d_in[1];
    const float* V    = (const float*)d_in[2];
    const float* mask = (const float*)d_in[3];
    const float* adj  = (const float*)d_in[4];
    const float* dist = (const float*)d_in[5];

    float* outp  = (float*)d_out;
    float* pattn = outp + (size_t)BB * HH * SDIM * DDIM;

    precompute_C_kernel<<<BB * SDIM, THREADS>>>(adj, dist, mask);

    cudaFuncSetAttribute(attn_mma_kernel,
                         cudaFuncAttributeMaxDynamicSharedMemorySize, SMEM_BYTES);
    dim3 grid(NKT, HH, BB);
    attn_mma_kernel<<<grid, THREADS, SMEM_BYTES>>>(Q, K, V, mask, outp, pattn);
}

// round 5
// speedup vs baseline: 3.8684x; 1.0959x over previous
#include <cuda_runtime.h>
#include <cuda_bf16.h>
#include <math_constants.h>
#include <cstdint>

#define BB 16
#define HH 16
#define SDIM 512
#define DDIM 64
#define QT 64
#define NKT 8
#define THREADS 512
#define SSTRW 524          // f32 words per strip row
#define WROWB 2096         // strip row bytes (524*4)
#define KSTRB 144          // K/Q tile row bytes (72 bf16)
#define VSTRB 144          // V tile row bytes

#define L_ATT 0.33f
#define L_DIST 0.33f
#define L_ADJ (1.0f - 0.33f - 0.33f)

#define OFF_Q    134144                // 64*2096
#define OFF_QLO  (OFF_Q + 9216)
#define OFF_B    (OFF_Q + 18432)
#define OFF_BLO  (OFF_B + 9216)
#define OFF_V    134144                // overlaps Q/K (phase-3 only)
#define OFF_VLO  (OFF_V + 36864)       // 256*144
#define OFF_RED  (OFF_V + 73728)       // 207872
#define RSTR     68
#define OFF_MASK (OFF_RED + 17408)     // 225280
#define SMEM_BYTES (OFF_MASK + 2048)   // 227328

__device__ float g_C[(size_t)BB * SDIM * SDIM];

__global__ __launch_bounds__(256) void precompute_C_kernel(
    const float* __restrict__ adj, const float* __restrict__ dist,
    const float* __restrict__ mask)
{
    int row = blockIdx.x;
    int b = row >> 9;
    const float* arow = adj  + (size_t)row * SDIM;
    const float* drow = dist + (size_t)row * SDIM;
    const float* mrow = mask + (size_t)b * SDIM;
    float* crow = g_C + (size_t)row * SDIM;
    int tid = threadIdx.x, w = tid >> 5, l = tid & 31;

    float a0 = arow[tid], a1 = arow[tid + 256];
    float d0 = drow[tid], d1 = drow[tid + 256];
    float m0 = mrow[tid], m1 = mrow[tid + 256];
    float x0 = (m0 == 0.0f) ? -CUDART_INF_F : -d0;
    float x1 = (m1 == 0.0f) ? -CUDART_INF_F : -d1;

    float asum = a0 + a1, xmax = fmaxf(x0, x1);
    #pragma unroll
    for (int o = 16; o > 0; o >>= 1) {
        asum += __shfl_xor_sync(0xffffffffu, asum, o);
        xmax = fmaxf(xmax, __shfl_xor_sync(0xffffffffu, xmax, o));
    }
    __shared__ float rs[8], rm[8], re[8];
    if (l == 0) { rs[w] = asum; rm[w] = xmax; }
    __syncthreads();
    float ts = 0.0f, tm = -CUDART_INF_F;
    #pragma unroll
    for (int i = 0; i < 8; i++) { ts += rs[i]; tm = fmaxf(tm, rm[i]); }

    float e0 = __expf(x0 - tm), e1 = __expf(x1 - tm), es = e0 + e1;
    #pragma unroll
    for (int o = 16; o > 0; o >>= 1) es += __shfl_xor_sync(0xffffffffu, es, o);
    if (l == 0) re[w] = es;
    __syncthreads();
    float te = 0.0f;
    #pragma unroll
    for (int i = 0; i < 8; i++) te += re[i];

    float inv_a = 1.0f / (ts + 1e-6f), inv_e = 1.0f / te;
    crow[tid]       = L_DIST * e0 * inv_e + L_ADJ * a0 * inv_a;
    crow[tid + 256] = L_DIST * e1 * inv_e + L_ADJ * a1 * inv_a;
}

__device__ __forceinline__ void mma_bf16(float* c, const uint32_t* a, const uint32_t* b) {
    asm volatile("mma.sync.aligned.m16n8k16.row.col.f32.bf16.bf16.f32 "
        "{%0,%1,%2,%3}, {%4,%5,%6,%7}, {%8,%9}, {%0,%1,%2,%3};"
        : "+f"(c[0]), "+f"(c[1]), "+f"(c[2]), "+f"(c[3])
        : "r"(a[0]), "r"(a[1]), "r"(a[2]), "r"(a[3]), "r"(b[0]), "r"(b[1]));
}
__device__ __forceinline__ void ldm_x4(uint32_t* r, uint32_t a) {
    asm volatile("ldmatrix.sync.aligned.m8n8.x4.shared.b16 {%0,%1,%2,%3}, [%4];"
        : "=r"(r[0]), "=r"(r[1]), "=r"(r[2]), "=r"(r[3]) : "r"(a));
}
__device__ __forceinline__ void ldm_x4t(uint32_t* r, uint32_t a) {
    asm volatile("ldmatrix.sync.aligned.m8n8.x4.trans.shared.b16 {%0,%1,%2,%3}, [%4];"
        : "=r"(r[0]), "=r"(r[1]), "=r"(r[2]), "=r"(r[3]) : "r"(a));
}
__device__ __forceinline__ uint32_t smem_u32(const void* p) {
    uint32_t a;
    asm("{ .reg .u64 t; cvta.to.shared.u64 t, %1; cvt.u32.u64 %0, t; }" : "=r"(a) : "l"(p));
    return a;
}
__device__ __forceinline__ uint32_t packbf(float lo, float hi) {
    uint32_t r;
    asm("cvt.rn.bf16x2.f32 %0, %1, %2;" : "=r"(r) : "f"(hi), "f"(lo));
    return r;
}
__device__ __forceinline__ float bfround(float x) {
    return __bfloat162float(__float2bfloat16_rn(x));
}

__global__ __launch_bounds__(512) void attn_mma_kernel(
    const float* __restrict__ Q, const float* __restrict__ K,
    const float* __restrict__ V, const float* __restrict__ mask,
    float* __restrict__ Og, float* __restrict__ Pg)
{
    extern __shared__ char smem[];
    float* sS = (float*)smem;
    float* sMask = (float*)(smem + OFF_MASK);
    float* sRed = (float*)(smem + OFF_RED);
    uint32_t sb = smem_u32(smem);

    int tid = threadIdx.x;
    int wid = tid >> 5, l = tid & 31;
    int lr = l >> 2, lc = l & 3;
    int lr8 = l & 7, lg = (l >> 3) & 1, kg4 = l >> 4;

    // phase-1 warp grid: m2 x n8
    int wm = wid >> 3, wn = wid & 7;
    // phase-3 warp grid: kg4 x mh2 x nh2
    int p3kg = wid >> 2, p3mh = (wid >> 1) & 1, p3nh = wid & 1;

    int qt = blockIdx.x, h = blockIdx.y, b = blockIdx.z;
    int q0 = qt * QT;
    size_t bh_ = (size_t)b * HH + h;
    const float* Qp = Q + (bh_ * SDIM + q0) * DDIM;
    const float* Kp = K + bh_ * SDIM * DDIM;
    const float* Vp = V + bh_ * SDIM * DDIM;
    const float* Mp = mask + (size_t)b * SDIM;
    const float* Cp = g_C + ((size_t)b * SDIM + q0) * SDIM;
    float* Op = Og + (bh_ * SDIM + q0) * DDIM;
    float* Pp = Pg + (bh_ * SDIM + q0) * SDIM;

    sMask[tid] = Mp[tid];

    // ---- Q (scaled 1/8) -> hi/lo bf16 smem ----
    {
        const float4* Q4 = (const float4*)Qp;
        #pragma unroll
        for (int t = 0; t < 2; ++t) {
            int idx = tid + 512 * t;
            float4 f = Q4[idx];
            int r = idx >> 4, c = (idx & 15) << 2;
            float v0 = f.x * 0.125f, v1 = f.y * 0.125f, v2 = f.z * 0.125f, v3 = f.w * 0.125f;
            uint32_t h01 = packbf(v0, v1), h23 = packbf(v2, v3);
            uint32_t l01 = packbf(v0 - bfround(v0), v1 - bfround(v1));
            uint32_t l23 = packbf(v2 - bfround(v2), v3 - bfround(v3));
            char* dst = smem + OFF_Q + r * KSTRB + 2 * c;
            *(uint2*)dst = make_uint2(h01, h23);
            *(uint2*)(dst + 9216) = make_uint2(l01, l23);
        }
    }
    float4 pf[2];
    {
        const float4* K4 = (const float4*)Kp;
        #pragma unroll
        for (int t = 0; t < 2; ++t) pf[t] = K4[tid + 512 * t];
    }
    __syncthreads();

    // ---- resident Q fragments (rows 32*wm..+31) ----
    uint32_t qah[2][4][4], qal[2][4][4];
    #pragma unroll
    for (int mt = 0; mt < 2; ++mt) {
        uint32_t ra = sb + OFF_Q + (32 * wm + 16 * mt + lr8 + 8 * lg) * KSTRB + 16 * kg4;
        #pragma unroll
        for (int ks = 0; ks < 4; ++ks) {
            ldm_x4(qah[mt][ks], ra + ks * 32);
            ldm_x4(qal[mt][ks], ra + 9216 + ks * 32);
        }
    }

    // ---- Phase 1: scores -> strip ----
    for (int kt = 0; kt < NKT; ++kt) {
        #pragma unroll
        for (int t = 0; t < 2; ++t) {
            int idx = tid + 512 * t;
            int r = idx >> 4, c = (idx & 15) << 2;
            float v0 = pf[t].x, v1 = pf[t].y, v2 = pf[t].z, v3 = pf[t].w;
            uint32_t h01 = packbf(v0, v1), h23 = packbf(v2, v3);
            uint32_t l01 = packbf(v0 - bfround(v0), v1 - bfround(v1));
            uint32_t l23 = packbf(v2 - bfround(v2), v3 - bfround(v3));
            char* dst = smem + OFF_B + r * KSTRB + 2 * c;
            *(uint2*)dst = make_uint2(h01, h23);
            *(uint2*)(dst + 9216) = make_uint2(l01, l23);
        }
        __syncthreads();
        if (kt < NKT - 1) {
            const float4* K4 = (const float4*)(Kp + (size_t)(kt + 1) * QT * DDIM);
            #pragma unroll
            for (int t = 0; t < 2; ++t) pf[t] = K4[tid + 512 * t];
        }

        float acc[2][4];
        #pragma unroll
        for (int mt = 0; mt < 2; ++mt)
            #pragma unroll
            for (int e = 0; e < 4; ++e) acc[mt][e] = 0.0f;

        #pragma unroll
        for (int ks = 0; ks < 4; ++ks) {
            // hybrid x4: lanes 0-15 hi (k-halves), 16-31 lo
            uint32_t bb[4];
            uint32_t rb = sb + OFF_B + (8 * wn + lr8) * KSTRB + 16 * lg + 9216 * kg4 + ks * 32;
            ldm_x4(bb, rb);
            #pragma unroll
            for (int mt = 0; mt < 2; ++mt) {
                mma_bf16(acc[mt], qah[mt][ks], bb);
                mma_bf16(acc[mt], qal[mt][ks], bb);
                mma_bf16(acc[mt], qah[mt][ks], bb + 2);
            }
        }
        #pragma unroll
        for (int mt = 0; mt < 2; ++mt) {
            int col = kt * 64 + 8 * wn + 2 * lc;
            int ar = 32 * wm + 16 * mt + lr;
            *(float2*)(sS + ar * SSTRW + col)       = make_float2(acc[mt][0], acc[mt][1]);
            *(float2*)(sS + (ar + 8) * SSTRW + col) = make_float2(acc[mt][2], acc[mt][3]);
        }
        __syncthreads();
    }

    // ---- Phase 2: softmax (4 rows/warp), p_attn out, blend -> W bf16 hi/lo in strip ----
    for (int rr = 0; rr < 4; ++rr) {
        int q = wid * 4 + rr;
        float* srow = sS + q * SSTRW;
        float v[16];
        #pragma unroll
        for (int t = 0; t < 4; ++t) {
            float4 f = *(float4*)(srow + l * 4 + 128 * t);
            int c0 = l * 4 + 128 * t;
            v[t*4+0] = (sMask[c0+0] == 0.0f) ? -1e12f : f.x;
            v[t*4+1] = (sMask[c0+1] == 0.0f) ? -1e12f : f.y;
            v[t*4+2] = (sMask[c0+2] == 0.0f) ? -1e12f : f.z;
            v[t*4+3] = (sMask[c0+3] == 0.0f) ? -1e12f : f.w;
        }
        float m = -CUDART_INF_F;
        #pragma unroll
        for (int t = 0; t < 16; ++t) m = fmaxf(m, v[t]);
        #pragma unroll
        for (int o = 16; o > 0; o >>= 1)
            m = fmaxf(m, __shfl_xor_sync(0xffffffffu, m, o));
        float sum = 0.0f;
        #pragma unroll
        for (int t = 0; t < 16; ++t) { v[t] = __expf(v[t] - m); sum += v[t]; }
        #pragma unroll
        for (int o = 16; o > 0; o >>= 1)
            sum += __shfl_xor_sync(0xffffffffu, sum, o);
        float inv = 1.0f / sum;
        __syncwarp();
        const float* Crow = Cp + (size_t)q * SDIM;
        float* Prow = Pp + (size_t)q * SDIM;
        char* Wrow = smem + q * WROWB;
        #pragma unroll
        for (int t = 0; t < 4; ++t) {
            int c0 = l * 4 + 128 * t;
            float4 p;
            p.x = v[t*4+0] * inv; p.y = v[t*4+1] * inv;
            p.z = v[t*4+2] * inv; p.w = v[t*4+3] * inv;
            __stcs((float4*)(Prow + c0), p);
            float4 cw = *(const float4*)(Crow + c0);
            float w0 = fmaf(L_ATT, p.x, cw.x), w1 = fmaf(L_ATT, p.y, cw.y);
            float w2 = fmaf(L_ATT, p.z, cw.z), w3 = fmaf(L_ATT, p.w, cw.w);
            uint32_t h01 = packbf(w0, w1), h23 = packbf(w2, w3);
            uint32_t l01 = packbf(w0 - bfround(w0), w1 - bfround(w1));
            uint32_t l23 = packbf(w2 - bfround(w2), w3 - bfround(w3));
            *(uint2*)(Wrow + 2 * c0)        = make_uint2(h01, h23);
            *(uint2*)(Wrow + 1040 + 2 * c0) = make_uint2(l01, l23);
        }
    }

    // ---- Phase 3: out = W @ V, k-split (kg4), V staged in 2 halves, no V dup ----
    float accO[2][4][4];
    #pragma unroll
    for (int mt = 0; mt < 2; ++mt)
        #pragma unroll
        for (int nj = 0; nj < 4; ++nj)
            #pragma unroll
            for (int e = 0; e < 4; ++e) accO[mt][nj][e] = 0.0f;

    for (int half = 0; half < 2; ++half) {
        __syncthreads();   // prev compute done (and phase 2 complete for half 0)
        {
            const float4* V4 = (const float4*)(Vp + (size_t)half * 256 * DDIM);
            #pragma unroll
            for (int t = 0; t < 8; ++t) {
                int idx = tid + 512 * t;
                float4 f = V4[idx];
                int kk = idx >> 4, d0 = (idx & 15) << 2;
                uint32_t h01 = packbf(f.x, f.y), h23 = packbf(f.z, f.w);
                uint32_t l01 = packbf(f.x - bfround(f.x), f.y - bfround(f.y));
                uint32_t l23 = packbf(f.z - bfround(f.z), f.w - bfround(f.w));
                char* dst = smem + OFF_V + kk * VSTRB + 2 * d0;
                *(uint2*)dst = make_uint2(h01, h23);
                *(uint2*)(dst + 36864) = make_uint2(l01, l23);
            }
        }
        __syncthreads();

        #pragma unroll
        for (int ks = 0; ks < 4; ++ks) {
            // V b-frags via ldmatrix.trans from natural [k][d] layout (hi+lo hybrid)
            uint32_t vb[4][4];
            #pragma unroll
            for (int nj = 0; nj < 4; ++nj) {
                uint32_t rbv = sb + OFF_V
                    + (p3kg * 64 + 16 * ks + lr8 + 8 * lg) * VSTRB
                    + 2 * (32 * p3nh + 8 * nj) + 36864 * kg4;
                ldm_x4t(vb[nj], rbv);
            }
            uint32_t koffB = 2u * (half * 256 + p3kg * 64 + 16 * ks);
            #pragma unroll
            for (int mt = 0; mt < 2; ++mt) {
                uint32_t ah[4], al[4];
                uint32_t ra = sb + (32 * p3mh + 16 * mt + lr8 + 8 * lg) * WROWB
                              + koffB + 16 * kg4;
                ldm_x4(ah, ra);
                ldm_x4(al, ra + 1040);
                #pragma unroll
                for (int nj = 0; nj < 4; ++nj) {
                    mma_bf16(accO[mt][nj], ah, vb[nj]);
                    mma_bf16(accO[mt][nj], al, vb[nj]);
                    mma_bf16(accO[mt][nj], ah, vb[nj] + 2);
                }
            }
        }
    }

    // ---- reduce 4 kg partials ----
    #pragma unroll
    for (int r = 0; r < 4; ++r) {
        __syncthreads();
        if (p3kg == r) {
            #pragma unroll
            for (int mt = 0; mt < 2; ++mt)
                #pragma unroll
                for (int nj = 0; nj < 4; ++nj) {
                    int row = 32 * p3mh + 16 * mt + lr;
                    int col = 32 * p3nh + 8 * nj + 2 * lc;
                    float2* p0 = (float2*)(sRed + row * RSTR + col);
                    float2* p1 = (float2*)(sRed + (row + 8) * RSTR + col);
                    if (r == 0) {
                        *p0 = make_float2(accO[mt][nj][0], accO[mt][nj][1]);
                        *p1 = make_float2(accO[mt][nj][2], accO[mt][nj][3]);
                    } else {
                        float2 a = *p0, bq = *p1;
                        a.x += accO[mt][nj][0]; a.y += accO[mt][nj][1];
                        bq.x += accO[mt][nj][2]; bq.y += accO[mt][nj][3];
                        *p0 = a; *p1 = bq;
                    }
                }
        }
    }
    __syncthreads();

    // ---- write out ----
    #pragma unroll
    for (int t = 0; t < 2; ++t) {
        int idx = tid + 512 * t;
        int row = idx >> 4, c0 = (idx & 15) << 2;
        float4 o = *(float4*)(sRed + row * RSTR + c0);
        *(float4*)(Op + row * DDIM + c0) = o;
    }
}

extern "C" void kernel_launch(void* const* d_in, const int* in_sizes, int n_in,
                              void* d_out, int out_size)
{
    const float* Q    = (const float*)d_in[0];
    const float* K    = (const float*)d_in[1];
    const float* V    = (const float*)d_in[2];
    const float* mask = (const float*)d_in[3];
    const float* adj  = (const float*)d_in[4];
    const float* dist = (const float*)d_in[5];

    float* outp  = (float*)d_out;
    float* pattn = outp + (size_t)BB * HH * SDIM * DDIM;

    precompute_C_kernel<<<BB * SDIM, 256>>>(adj, dist, mask);

    cudaFuncSetAttribute(attn_mma_kernel,
                         cudaFuncAttributeMaxDynamicSharedMemorySize, SMEM_BYTES);
    dim3 grid(NKT, HH, BB);
    attn_mma_kernel<<<grid, THREADS, SMEM_BYTES>>>(Q, K, V, mask, outp, pattn);
}

// round 6
// speedup vs baseline: 3.8717x; 1.0009x over previous
#include <cuda_runtime.h>
#include <cuda_bf16.h>
#include <math_constants.h>
#include <cstdint>

#define BB 16
#define HH 16
#define SDIM 512
#define DDIM 64
#define QT 64
#define NKT 8
#define THREADS 512
#define SSTRW 524          // f32 words per strip row
#define WROWB 2096         // strip row bytes (524*4)
#define KSTRB 144          // K/Q tile row bytes (72 bf16)
#define VSTRB 144          // V tile row bytes

#define L_ATT 0.33f
#define L_DIST 0.33f
#define L_ADJ (1.0f - 0.33f - 0.33f)

#define OFF_Q    134144                // 64*2096
#define OFF_QLO  (OFF_Q + 9216)
#define OFF_B    (OFF_Q + 18432)
#define OFF_BLO  (OFF_B + 9216)
#define OFF_V    134144                // overlaps Q/K (phase-3 only)
#define OFF_VLO  (OFF_V + 36864)       // 256*144
#define OFF_RED  (OFF_V + 73728)       // 207872
#define RSTR     68
#define OFF_MASK (OFF_RED + 17408)     // 225280
#define SMEM_BYTES (OFF_MASK + 2048)   // 227328

__device__ float g_C[(size_t)BB * SDIM * SDIM];

__global__ __launch_bounds__(256) void precompute_C_kernel(
    const float* __restrict__ adj, const float* __restrict__ dist,
    const float* __restrict__ mask)
{
    int row = blockIdx.x;
    int b = row >> 9;
    const float* arow = adj  + (size_t)row * SDIM;
    const float* drow = dist + (size_t)row * SDIM;
    const float* mrow = mask + (size_t)b * SDIM;
    float* crow = g_C + (size_t)row * SDIM;
    int tid = threadIdx.x, w = tid >> 5, l = tid & 31;

    float a0 = arow[tid], a1 = arow[tid + 256];
    float d0 = drow[tid], d1 = drow[tid + 256];
    float m0 = mrow[tid], m1 = mrow[tid + 256];
    float x0 = (m0 == 0.0f) ? -CUDART_INF_F : -d0;
    float x1 = (m1 == 0.0f) ? -CUDART_INF_F : -d1;

    float asum = a0 + a1, xmax = fmaxf(x0, x1);
    #pragma unroll
    for (int o = 16; o > 0; o >>= 1) {
        asum += __shfl_xor_sync(0xffffffffu, asum, o);
        xmax = fmaxf(xmax, __shfl_xor_sync(0xffffffffu, xmax, o));
    }
    __shared__ float rs[8], rm[8], re[8];
    if (l == 0) { rs[w] = asum; rm[w] = xmax; }
    __syncthreads();
    float ts = 0.0f, tm = -CUDART_INF_F;
    #pragma unroll
    for (int i = 0; i < 8; i++) { ts += rs[i]; tm = fmaxf(tm, rm[i]); }

    float e0 = __expf(x0 - tm), e1 = __expf(x1 - tm), es = e0 + e1;
    #pragma unroll
    for (int o = 16; o > 0; o >>= 1) es += __shfl_xor_sync(0xffffffffu, es, o);
    if (l == 0) re[w] = es;
    __syncthreads();
    float te = 0.0f;
    #pragma unroll
    for (int i = 0; i < 8; i++) te += re[i];

    float inv_a = 1.0f / (ts + 1e-6f), inv_e = 1.0f / te;
    crow[tid]       = L_DIST * e0 * inv_e + L_ADJ * a0 * inv_a;
    crow[tid + 256] = L_DIST * e1 * inv_e + L_ADJ * a1 * inv_a;
}

__device__ __forceinline__ void mma_bf16(float* c, const uint32_t* a, const uint32_t* b) {
    asm volatile("mma.sync.aligned.m16n8k16.row.col.f32.bf16.bf16.f32 "
        "{%0,%1,%2,%3}, {%4,%5,%6,%7}, {%8,%9}, {%0,%1,%2,%3};"
        : "+f"(c[0]), "+f"(c[1]), "+f"(c[2]), "+f"(c[3])
        : "r"(a[0]), "r"(a[1]), "r"(a[2]), "r"(a[3]), "r"(b[0]), "r"(b[1]));
}
__device__ __forceinline__ void ldm_x4(uint32_t* r, uint32_t a) {
    asm volatile("ldmatrix.sync.aligned.m8n8.x4.shared.b16 {%0,%1,%2,%3}, [%4];"
        : "=r"(r[0]), "=r"(r[1]), "=r"(r[2]), "=r"(r[3]) : "r"(a));
}
__device__ __forceinline__ void ldm_x4t(uint32_t* r, uint32_t a) {
    asm volatile("ldmatrix.sync.aligned.m8n8.x4.trans.shared.b16 {%0,%1,%2,%3}, [%4];"
        : "=r"(r[0]), "=r"(r[1]), "=r"(r[2]), "=r"(r[3]) : "r"(a));
}
__device__ __forceinline__ uint32_t smem_u32(const void* p) {
    uint32_t a;
    asm("{ .reg .u64 t; cvta.to.shared.u64 t, %1; cvt.u32.u64 %0, t; }" : "=r"(a) : "l"(p));
    return a;
}
__device__ __forceinline__ uint32_t packbf(float lo, float hi) {
    uint32_t r;
    asm("cvt.rn.bf16x2.f32 %0, %1, %2;" : "=r"(r) : "f"(hi), "f"(lo));
    return r;
}
__device__ __forceinline__ float bfround(float x) {
    return __bfloat162float(__float2bfloat16_rn(x));
}

__global__ __launch_bounds__(512) void attn_mma_kernel(
    const float* __restrict__ Q, const float* __restrict__ K,
    const float* __restrict__ V, const float* __restrict__ mask,
    float* __restrict__ Og, float* __restrict__ Pg)
{
    extern __shared__ char smem[];
    float* sS = (float*)smem;
    float* sMask = (float*)(smem + OFF_MASK);
    float* sRed = (float*)(smem + OFF_RED);
    uint32_t sb = smem_u32(smem);

    int tid = threadIdx.x;
    int wid = tid >> 5, l = tid & 31;
    int lr = l >> 2, lc = l & 3;
    int lr8 = l & 7, lg = (l >> 3) & 1, kg4 = l >> 4;

    // phase-1 warp grid: m2 x n8
    int wm = wid >> 3, wn = wid & 7;
    // phase-3 warp grid: kg4 x mh2 x nh2
    int p3kg = wid >> 2, p3mh = (wid >> 1) & 1, p3nh = wid & 1;

    int qt = blockIdx.x, h = blockIdx.y, b = blockIdx.z;
    int q0 = qt * QT;
    size_t bh_ = (size_t)b * HH + h;
    const float* Qp = Q + (bh_ * SDIM + q0) * DDIM;
    const float* Kp = K + bh_ * SDIM * DDIM;
    const float* Vp = V + bh_ * SDIM * DDIM;
    const float* Mp = mask + (size_t)b * SDIM;
    const float* Cp = g_C + ((size_t)b * SDIM + q0) * SDIM;
    float* Op = Og + (bh_ * SDIM + q0) * DDIM;
    float* Pp = Pg + (bh_ * SDIM + q0) * SDIM;

    sMask[tid] = Mp[tid];

    // ---- Q (scaled 1/8) -> hi/lo bf16 smem ----
    {
        const float4* Q4 = (const float4*)Qp;
        #pragma unroll
        for (int t = 0; t < 2; ++t) {
            int idx = tid + 512 * t;
            float4 f = Q4[idx];
            int r = idx >> 4, c = (idx & 15) << 2;
            float v0 = f.x * 0.125f, v1 = f.y * 0.125f, v2 = f.z * 0.125f, v3 = f.w * 0.125f;
            uint32_t h01 = packbf(v0, v1), h23 = packbf(v2, v3);
            uint32_t l01 = packbf(v0 - bfround(v0), v1 - bfround(v1));
            uint32_t l23 = packbf(v2 - bfround(v2), v3 - bfround(v3));
            char* dst = smem + OFF_Q + r * KSTRB + 2 * c;
            *(uint2*)dst = make_uint2(h01, h23);
            *(uint2*)(dst + 9216) = make_uint2(l01, l23);
        }
    }
    float4 pf[2];
    {
        const float4* K4 = (const float4*)Kp;
        #pragma unroll
        for (int t = 0; t < 2; ++t) pf[t] = K4[tid + 512 * t];
    }
    __syncthreads();

    // ---- resident Q fragments (rows 32*wm..+31) ----
    uint32_t qah[2][4][4], qal[2][4][4];
    #pragma unroll
    for (int mt = 0; mt < 2; ++mt) {
        uint32_t ra = sb + OFF_Q + (32 * wm + 16 * mt + lr8 + 8 * lg) * KSTRB + 16 * kg4;
        #pragma unroll
        for (int ks = 0; ks < 4; ++ks) {
            ldm_x4(qah[mt][ks], ra + ks * 32);
            ldm_x4(qal[mt][ks], ra + 9216 + ks * 32);
        }
    }

    // ---- Phase 1: scores -> strip ----
    for (int kt = 0; kt < NKT; ++kt) {
        #pragma unroll
        for (int t = 0; t < 2; ++t) {
            int idx = tid + 512 * t;
            int r = idx >> 4, c = (idx & 15) << 2;
            float v0 = pf[t].x, v1 = pf[t].y, v2 = pf[t].z, v3 = pf[t].w;
            uint32_t h01 = packbf(v0, v1), h23 = packbf(v2, v3);
            uint32_t l01 = packbf(v0 - bfround(v0), v1 - bfround(v1));
            uint32_t l23 = packbf(v2 - bfround(v2), v3 - bfround(v3));
            char* dst = smem + OFF_B + r * KSTRB + 2 * c;
            *(uint2*)dst = make_uint2(h01, h23);
            *(uint2*)(dst + 9216) = make_uint2(l01, l23);
        }
        __syncthreads();
        if (kt < NKT - 1) {
            const float4* K4 = (const float4*)(Kp + (size_t)(kt + 1) * QT * DDIM);
            #pragma unroll
            for (int t = 0; t < 2; ++t) pf[t] = K4[tid + 512 * t];
        }

        float acc[2][4];
        #pragma unroll
        for (int mt = 0; mt < 2; ++mt)
            #pragma unroll
            for (int e = 0; e < 4; ++e) acc[mt][e] = 0.0f;

        #pragma unroll
        for (int ks = 0; ks < 4; ++ks) {
            // hybrid x4: lanes 0-15 hi (k-halves), 16-31 lo
            uint32_t bb[4];
            uint32_t rb = sb + OFF_B + (8 * wn + lr8) * KSTRB + 16 * lg + 9216 * kg4 + ks * 32;
            ldm_x4(bb, rb);
            #pragma unroll
            for (int mt = 0; mt < 2; ++mt) {
                mma_bf16(acc[mt], qah[mt][ks], bb);
                mma_bf16(acc[mt], qal[mt][ks], bb);
                mma_bf16(acc[mt], qah[mt][ks], bb + 2);
            }
        }
        #pragma unroll
        for (int mt = 0; mt < 2; ++mt) {
            int col = kt * 64 + 8 * wn + 2 * lc;
            int ar = 32 * wm + 16 * mt + lr;
            *(float2*)(sS + ar * SSTRW + col)       = make_float2(acc[mt][0], acc[mt][1]);
            *(float2*)(sS + (ar + 8) * SSTRW + col) = make_float2(acc[mt][2], acc[mt][3]);
        }
        __syncthreads();
    }

    // ---- Phase 2: softmax (4 rows/warp), p_attn out, blend -> W bf16 hi/lo in strip ----
    for (int rr = 0; rr < 4; ++rr) {
        int q = wid * 4 + rr;
        float* srow = sS + q * SSTRW;
        float v[16];
        #pragma unroll
        for (int t = 0; t < 4; ++t) {
            float4 f = *(float4*)(srow + l * 4 + 128 * t);
            int c0 = l * 4 + 128 * t;
            v[t*4+0] = (sMask[c0+0] == 0.0f) ? -1e12f : f.x;
            v[t*4+1] = (sMask[c0+1] == 0.0f) ? -1e12f : f.y;
            v[t*4+2] = (sMask[c0+2] == 0.0f) ? -1e12f : f.z;
            v[t*4+3] = (sMask[c0+3] == 0.0f) ? -1e12f : f.w;
        }
        float m = -CUDART_INF_F;
        #pragma unroll
        for (int t = 0; t < 16; ++t) m = fmaxf(m, v[t]);
        #pragma unroll
        for (int o = 16; o > 0; o >>= 1)
            m = fmaxf(m, __shfl_xor_sync(0xffffffffu, m, o));
        float sum = 0.0f;
        #pragma unroll
        for (int t = 0; t < 16; ++t) { v[t] = __expf(v[t] - m); sum += v[t]; }
        #pragma unroll
        for (int o = 16; o > 0; o >>= 1)
            sum += __shfl_xor_sync(0xffffffffu, sum, o);
        float inv = 1.0f / sum;
        __syncwarp();
        const float* Crow = Cp + (size_t)q * SDIM;
        float* Prow = Pp + (size_t)q * SDIM;
        char* Wrow = smem + q * WROWB;
        #pragma unroll
        for (int t = 0; t < 4; ++t) {
            int c0 = l * 4 + 128 * t;
            float4 p;
            p.x = v[t*4+0] * inv; p.y = v[t*4+1] * inv;
            p.z = v[t*4+2] * inv; p.w = v[t*4+3] * inv;
            __stcs((float4*)(Prow + c0), p);
            float4 cw = *(const float4*)(Crow + c0);
            float w0 = fmaf(L_ATT, p.x, cw.x), w1 = fmaf(L_ATT, p.y, cw.y);
            float w2 = fmaf(L_ATT, p.z, cw.z), w3 = fmaf(L_ATT, p.w, cw.w);
            uint32_t h01 = packbf(w0, w1), h23 = packbf(w2, w3);
            uint32_t l01 = packbf(w0 - bfround(w0), w1 - bfround(w1));
            uint32_t l23 = packbf(w2 - bfround(w2), w3 - bfround(w3));
            *(uint2*)(Wrow + 2 * c0)        = make_uint2(h01, h23);
            *(uint2*)(Wrow + 1040 + 2 * c0) = make_uint2(l01, l23);
        }
    }

    // ---- Phase 3: out = W @ V, k-split (kg4), V staged in 2 halves, no V dup ----
    float accO[2][4][4];
    #pragma unroll
    for (int mt = 0; mt < 2; ++mt)
        #pragma unroll
        for (int nj = 0; nj < 4; ++nj)
            #pragma unroll
            for (int e = 0; e < 4; ++e) accO[mt][nj][e] = 0.0f;

    for (int half = 0; half < 2; ++half) {
        __syncthreads();   // prev compute done (and phase 2 complete for half 0)
        {
            const float4* V4 = (const float4*)(Vp + (size_t)half * 256 * DDIM);
            #pragma unroll
            for (int t = 0; t < 8; ++t) {
                int idx = tid + 512 * t;
                float4 f = V4[idx];
                int kk = idx >> 4, d0 = (idx & 15) << 2;
                uint32_t h01 = packbf(f.x, f.y), h23 = packbf(f.z, f.w);
                uint32_t l01 = packbf(f.x - bfround(f.x), f.y - bfround(f.y));
                uint32_t l23 = packbf(f.z - bfround(f.z), f.w - bfround(f.w));
                char* dst = smem + OFF_V + kk * VSTRB + 2 * d0;
                *(uint2*)dst = make_uint2(h01, h23);
                *(uint2*)(dst + 36864) = make_uint2(l01, l23);
            }
        }
        __syncthreads();

        #pragma unroll
        for (int ks = 0; ks < 4; ++ks) {
            // V b-frags via ldmatrix.trans from natural [k][d] layout (hi+lo hybrid)
            uint32_t vb[4][4];
            #pragma unroll
            for (int nj = 0; nj < 4; ++nj) {
                uint32_t rbv = sb + OFF_V
                    + (p3kg * 64 + 16 * ks + lr8 + 8 * lg) * VSTRB
                    + 2 * (32 * p3nh + 8 * nj) + 36864 * kg4;
                ldm_x4t(vb[nj], rbv);
            }
            uint32_t koffB = 2u * (half * 256 + p3kg * 64 + 16 * ks);
            #pragma unroll
            for (int mt = 0; mt < 2; ++mt) {
                uint32_t ah[4], al[4];
                uint32_t ra = sb + (32 * p3mh + 16 * mt + lr8 + 8 * lg) * WROWB
                              + koffB + 16 * kg4;
                ldm_x4(ah, ra);
                ldm_x4(al, ra + 1040);
                #pragma unroll
                for (int nj = 0; nj < 4; ++nj) {
                    mma_bf16(accO[mt][nj], ah, vb[nj]);
                    mma_bf16(accO[mt][nj], al, vb[nj]);
                    mma_bf16(accO[mt][nj], ah, vb[nj] + 2);
                }
            }
        }
    }

    // ---- reduce 4 kg partials ----
    #pragma unroll
    for (int r = 0; r < 4; ++r) {
        __syncthreads();
        if (p3kg == r) {
            #pragma unroll
            for (int mt = 0; mt < 2; ++mt)
                #pragma unroll
                for (int nj = 0; nj < 4; ++nj) {
                    int row = 32 * p3mh + 16 * mt + lr;
                    int col = 32 * p3nh + 8 * nj + 2 * lc;
                    float2* p0 = (float2*)(sRed + row * RSTR + col);
                    float2* p1 = (float2*)(sRed + (row + 8) * RSTR + col);
                    if (r == 0) {
                        *p0 = make_float2(accO[mt][nj][0], accO[mt][nj][1]);
                        *p1 = make_float2(accO[mt][nj][2], accO[mt][nj][3]);
                    } else {
                        float2 a = *p0, bq = *p1;
                        a.x += accO[mt][nj][0]; a.y += accO[mt][nj][1];
                        bq.x += accO[mt][nj][2]; bq.y += accO[mt][nj][3];
                        *p0 = a; *p1 = bq;
                    }
                }
        }
    }
    __syncthreads();

    // ---- write out ----
    #pragma unroll
    for (int t = 0; t < 2; ++t) {
        int idx = tid + 512 * t;
        int row = idx >> 4, c0 = (idx & 15) << 2;
        float4 o = *(float4*)(sRed + row * RSTR + c0);
        *(float4*)(Op + row * DDIM + c0) = o;
    }
}

extern "C" void kernel_launch(void* const* d_in, const int* in_sizes, int n_in,
                              void* d_out, int out_size)
{
    const float* Q    = (const float*)d_in[0];
    const float* K    = (const float*)d_in[1];
    const float* V    = (const float*)d_in[2];
    const float* mask = (const float*)d_in[3];
    const float* adj  = (const float*)d_in[4];
    const float* dist = (const float*)d_in[5];

    float* outp  = (float*)d_out;
    float* pattn = outp + (size_t)BB * HH * SDIM * DDIM;

    precompute_C_kernel<<<BB * SDIM, 256>>>(adj, dist, mask);

    cudaFuncSetAttribute(attn_mma_kernel,
                         cudaFuncAttributeMaxDynamicSharedMemorySize, SMEM_BYTES);
    dim3 grid(NKT, HH, BB);
    attn_mma_kernel<<<grid, THREADS, SMEM_BYTES>>>(Q, K, V, mask, outp, pattn);
}

// round 7
// speedup vs baseline: 3.8757x; 1.0010x over previous
#include <cuda_runtime.h>
#include <cuda_bf16.h>
#include <math_constants.h>
#include <cstdint>

#define BB 16
#define HH 16
#define SDIM 512
#define DDIM 64
#define QT 64
#define NKT 8
#define THREADS 512
#define SSTRW 524          // f32 words per strip row
#define WROWB 2096         // strip row bytes (524*4)
#define KSTRB 144          // K/Q tile row bytes (72 bf16)
#define VSTRB 144          // V tile row bytes

#define L_ATT 0.33f
#define L_DIST 0.33f
#define L_ADJ (1.0f - 0.33f - 0.33f)

#define OFF_Q    134144                // 64*2096
#define OFF_QLO  (OFF_Q + 9216)
#define OFF_B    (OFF_Q + 18432)
#define OFF_BLO  (OFF_B + 9216)
#define OFF_V    134144                // overlaps Q/K (phase-3 only)
#define OFF_VLO  (OFF_V + 36864)       // 256*144
#define OFF_RED  (OFF_V + 73728)       // 207872
#define RSTR     68
#define OFF_MASK (OFF_RED + 17408)     // 225280
#define SMEM_BYTES (OFF_MASK + 2048)   // 227328

__device__ float g_C[(size_t)BB * SDIM * SDIM];

__global__ __launch_bounds__(256) void precompute_C_kernel(
    const float* __restrict__ adj, const float* __restrict__ dist,
    const float* __restrict__ mask)
{
    int row = blockIdx.x;
    int b = row >> 9;
    const float* arow = adj  + (size_t)row * SDIM;
    const float* drow = dist + (size_t)row * SDIM;
    const float* mrow = mask + (size_t)b * SDIM;
    float* crow = g_C + (size_t)row * SDIM;
    int tid = threadIdx.x, w = tid >> 5, l = tid & 31;

    float a0 = arow[tid], a1 = arow[tid + 256];
    float d0 = drow[tid], d1 = drow[tid + 256];
    float m0 = mrow[tid], m1 = mrow[tid + 256];
    float x0 = (m0 == 0.0f) ? -CUDART_INF_F : -d0;
    float x1 = (m1 == 0.0f) ? -CUDART_INF_F : -d1;

    float asum = a0 + a1, xmax = fmaxf(x0, x1);
    #pragma unroll
    for (int o = 16; o > 0; o >>= 1) {
        asum += __shfl_xor_sync(0xffffffffu, asum, o);
        xmax = fmaxf(xmax, __shfl_xor_sync(0xffffffffu, xmax, o));
    }
    __shared__ float rs[8], rm[8], re[8];
    if (l == 0) { rs[w] = asum; rm[w] = xmax; }
    __syncthreads();
    float ts = 0.0f, tm = -CUDART_INF_F;
    #pragma unroll
    for (int i = 0; i < 8; i++) { ts += rs[i]; tm = fmaxf(tm, rm[i]); }

    float e0 = __expf(x0 - tm), e1 = __expf(x1 - tm), es = e0 + e1;
    #pragma unroll
    for (int o = 16; o > 0; o >>= 1) es += __shfl_xor_sync(0xffffffffu, es, o);
    if (l == 0) re[w] = es;
    __syncthreads();
    float te = 0.0f;
    #pragma unroll
    for (int i = 0; i < 8; i++) te += re[i];

    float inv_a = 1.0f / (ts + 1e-6f), inv_e = 1.0f / te;
    crow[tid]       = L_DIST * e0 * inv_e + L_ADJ * a0 * inv_a;
    crow[tid + 256] = L_DIST * e1 * inv_e + L_ADJ * a1 * inv_a;
}

__device__ __forceinline__ void mma_bf16(float* c, const uint32_t* a, const uint32_t* b) {
    asm volatile("mma.sync.aligned.m16n8k16.row.col.f32.bf16.bf16.f32 "
        "{%0,%1,%2,%3}, {%4,%5,%6,%7}, {%8,%9}, {%0,%1,%2,%3};"
        : "+f"(c[0]), "+f"(c[1]), "+f"(c[2]), "+f"(c[3])
        : "r"(a[0]), "r"(a[1]), "r"(a[2]), "r"(a[3]), "r"(b[0]), "r"(b[1]));
}
__device__ __forceinline__ void ldm_x4(uint32_t* r, uint32_t a) {
    asm volatile("ldmatrix.sync.aligned.m8n8.x4.shared.b16 {%0,%1,%2,%3}, [%4];"
        : "=r"(r[0]), "=r"(r[1]), "=r"(r[2]), "=r"(r[3]) : "r"(a));
}
__device__ __forceinline__ void ldm_x4t(uint32_t* r, uint32_t a) {
    asm volatile("ldmatrix.sync.aligned.m8n8.x4.trans.shared.b16 {%0,%1,%2,%3}, [%4];"
        : "=r"(r[0]), "=r"(r[1]), "=r"(r[2]), "=r"(r[3]) : "r"(a));
}
__device__ __forceinline__ uint32_t smem_u32(const void* p) {
    uint32_t a;
    asm("{ .reg .u64 t; cvta.to.shared.u64 t, %1; cvt.u32.u64 %0, t; }" : "=r"(a) : "l"(p));
    return a;
}
__device__ __forceinline__ uint32_t packbf(float lo, float hi) {
    uint32_t r;
    asm("cvt.rn.bf16x2.f32 %0, %1, %2;" : "=r"(r) : "f"(hi), "f"(lo));
    return r;
}
__device__ __forceinline__ float bfround(float x) {
    return __bfloat162float(__float2bfloat16_rn(x));
}

__global__ __launch_bounds__(512) void attn_mma_kernel(
    const float* __restrict__ Q, const float* __restrict__ K,
    const float* __restrict__ V, const float* __restrict__ mask,
    float* __restrict__ Og, float* __restrict__ Pg)
{
    extern __shared__ char smem[];
    float* sS = (float*)smem;
    float* sMask = (float*)(smem + OFF_MASK);
    float* sRed = (float*)(smem + OFF_RED);
    uint32_t sb = smem_u32(smem);

    int tid = threadIdx.x;
    int wid = tid >> 5, l = tid & 31;
    int lr = l >> 2, lc = l & 3;
    int lr8 = l & 7, lg = (l >> 3) & 1, kg4 = l >> 4;

    // phase-1 warp grid: m2 x n8
    int wm = wid >> 3, wn = wid & 7;
    // phase-3 warp grid: kg4 x mh2 x nh2
    int p3kg = wid >> 2, p3mh = (wid >> 1) & 1, p3nh = wid & 1;

    int qt = blockIdx.x, h = blockIdx.y, b = blockIdx.z;
    int q0 = qt * QT;
    size_t bh_ = (size_t)b * HH + h;
    const float* Qp = Q + (bh_ * SDIM + q0) * DDIM;
    const float* Kp = K + bh_ * SDIM * DDIM;
    const float* Vp = V + bh_ * SDIM * DDIM;
    const float* Mp = mask + (size_t)b * SDIM;
    const float* Cp = g_C + ((size_t)b * SDIM + q0) * SDIM;
    float* Op = Og + (bh_ * SDIM + q0) * DDIM;
    float* Pp = Pg + (bh_ * SDIM + q0) * SDIM;

    sMask[tid] = Mp[tid];

    // ---- Q (scaled 1/8) -> hi/lo bf16 smem ----
    {
        const float4* Q4 = (const float4*)Qp;
        #pragma unroll
        for (int t = 0; t < 2; ++t) {
            int idx = tid + 512 * t;
            float4 f = Q4[idx];
            int r = idx >> 4, c = (idx & 15) << 2;
            float v0 = f.x * 0.125f, v1 = f.y * 0.125f, v2 = f.z * 0.125f, v3 = f.w * 0.125f;
            uint32_t h01 = packbf(v0, v1), h23 = packbf(v2, v3);
            uint32_t l01 = packbf(v0 - bfround(v0), v1 - bfround(v1));
            uint32_t l23 = packbf(v2 - bfround(v2), v3 - bfround(v3));
            char* dst = smem + OFF_Q + r * KSTRB + 2 * c;
            *(uint2*)dst = make_uint2(h01, h23);
            *(uint2*)(dst + 9216) = make_uint2(l01, l23);
        }
    }
    float4 pf[2];
    {
        const float4* K4 = (const float4*)Kp;
        #pragma unroll
        for (int t = 0; t < 2; ++t) pf[t] = K4[tid + 512 * t];
    }
    __syncthreads();

    // ---- resident Q fragments (rows 32*wm..+31) ----
    uint32_t qah[2][4][4], qal[2][4][4];
    #pragma unroll
    for (int mt = 0; mt < 2; ++mt) {
        uint32_t ra = sb + OFF_Q + (32 * wm + 16 * mt + lr8 + 8 * lg) * KSTRB + 16 * kg4;
        #pragma unroll
        for (int ks = 0; ks < 4; ++ks) {
            ldm_x4(qah[mt][ks], ra + ks * 32);
            ldm_x4(qal[mt][ks], ra + 9216 + ks * 32);
        }
    }

    // ---- Phase 1: scores -> strip ----
    for (int kt = 0; kt < NKT; ++kt) {
        #pragma unroll
        for (int t = 0; t < 2; ++t) {
            int idx = tid + 512 * t;
            int r = idx >> 4, c = (idx & 15) << 2;
            float v0 = pf[t].x, v1 = pf[t].y, v2 = pf[t].z, v3 = pf[t].w;
            uint32_t h01 = packbf(v0, v1), h23 = packbf(v2, v3);
            uint32_t l01 = packbf(v0 - bfround(v0), v1 - bfround(v1));
            uint32_t l23 = packbf(v2 - bfround(v2), v3 - bfround(v3));
            char* dst = smem + OFF_B + r * KSTRB + 2 * c;
            *(uint2*)dst = make_uint2(h01, h23);
            *(uint2*)(dst + 9216) = make_uint2(l01, l23);
        }
        __syncthreads();
        if (kt < NKT - 1) {
            const float4* K4 = (const float4*)(Kp + (size_t)(kt + 1) * QT * DDIM);
            #pragma unroll
            for (int t = 0; t < 2; ++t) pf[t] = K4[tid + 512 * t];
        }

        float acc[2][4];
        #pragma unroll
        for (int mt = 0; mt < 2; ++mt)
            #pragma unroll
            for (int e = 0; e < 4; ++e) acc[mt][e] = 0.0f;

        #pragma unroll
        for (int ks = 0; ks < 4; ++ks) {
            // hybrid x4: lanes 0-15 hi (k-halves), 16-31 lo
            uint32_t bb[4];
            uint32_t rb = sb + OFF_B + (8 * wn + lr8) * KSTRB + 16 * lg + 9216 * kg4 + ks * 32;
            ldm_x4(bb, rb);
            #pragma unroll
            for (int mt = 0; mt < 2; ++mt) {
                mma_bf16(acc[mt], qah[mt][ks], bb);
                mma_bf16(acc[mt], qal[mt][ks], bb);
                mma_bf16(acc[mt], qah[mt][ks], bb + 2);
            }
        }
        #pragma unroll
        for (int mt = 0; mt < 2; ++mt) {
            int col = kt * 64 + 8 * wn + 2 * lc;
            int ar = 32 * wm + 16 * mt + lr;
            *(float2*)(sS + ar * SSTRW + col)       = make_float2(acc[mt][0], acc[mt][1]);
            *(float2*)(sS + (ar + 8) * SSTRW + col) = make_float2(acc[mt][2], acc[mt][3]);
        }
        __syncthreads();
    }

    // ---- Phase 2: softmax (4 rows/warp), p_attn out, blend -> W bf16 hi/lo in strip ----
    for (int rr = 0; rr < 4; ++rr) {
        int q = wid * 4 + rr;
        float* srow = sS + q * SSTRW;
        float v[16];
        #pragma unroll
        for (int t = 0; t < 4; ++t) {
            float4 f = *(float4*)(srow + l * 4 + 128 * t);
            int c0 = l * 4 + 128 * t;
            v[t*4+0] = (sMask[c0+0] == 0.0f) ? -1e12f : f.x;
            v[t*4+1] = (sMask[c0+1] == 0.0f) ? -1e12f : f.y;
            v[t*4+2] = (sMask[c0+2] == 0.0f) ? -1e12f : f.z;
            v[t*4+3] = (sMask[c0+3] == 0.0f) ? -1e12f : f.w;
        }
        float m = -CUDART_INF_F;
        #pragma unroll
        for (int t = 0; t < 16; ++t) m = fmaxf(m, v[t]);
        #pragma unroll
        for (int o = 16; o > 0; o >>= 1)
            m = fmaxf(m, __shfl_xor_sync(0xffffffffu, m, o));
        float sum = 0.0f;
        #pragma unroll
        for (int t = 0; t < 16; ++t) { v[t] = __expf(v[t] - m); sum += v[t]; }
        #pragma unroll
        for (int o = 16; o > 0; o >>= 1)
            sum += __shfl_xor_sync(0xffffffffu, sum, o);
        float inv = 1.0f / sum;
        __syncwarp();
        const float* Crow = Cp + (size_t)q * SDIM;
        float* Prow = Pp + (size_t)q * SDIM;
        char* Wrow = smem + q * WROWB;
        #pragma unroll
        for (int t = 0; t < 4; ++t) {
            int c0 = l * 4 + 128 * t;
            float4 p;
            p.x = v[t*4+0] * inv; p.y = v[t*4+1] * inv;
            p.z = v[t*4+2] * inv; p.w = v[t*4+3] * inv;
            __stcs((float4*)(Prow + c0), p);
            float4 cw = *(const float4*)(Crow + c0);
            float w0 = fmaf(L_ATT, p.x, cw.x), w1 = fmaf(L_ATT, p.y, cw.y);
            float w2 = fmaf(L_ATT, p.z, cw.z), w3 = fmaf(L_ATT, p.w, cw.w);
            uint32_t h01 = packbf(w0, w1), h23 = packbf(w2, w3);
            uint32_t l01 = packbf(w0 - bfround(w0), w1 - bfround(w1));
            uint32_t l23 = packbf(w2 - bfround(w2), w3 - bfround(w3));
            *(uint2*)(Wrow + 2 * c0)        = make_uint2(h01, h23);
            *(uint2*)(Wrow + 1040 + 2 * c0) = make_uint2(l01, l23);
        }
    }

    // ---- Phase 3: out = W @ V, k-split (kg4), V staged in 2 halves, no V dup ----
    float accO[2][4][4];
    #pragma unroll
    for (int mt = 0; mt < 2; ++mt)
        #pragma unroll
        for (int nj = 0; nj < 4; ++nj)
            #pragma unroll
            for (int e = 0; e < 4; ++e) accO[mt][nj][e] = 0.0f;

    for (int half = 0; half < 2; ++half) {
        __syncthreads();   // prev compute done (and phase 2 complete for half 0)
        {
            const float4* V4 = (const float4*)(Vp + (size_t)half * 256 * DDIM);
            #pragma unroll
            for (int t = 0; t < 8; ++t) {
                int idx = tid + 512 * t;
                float4 f = V4[idx];
                int kk = idx >> 4, d0 = (idx & 15) << 2;
                uint32_t h01 = packbf(f.x, f.y), h23 = packbf(f.z, f.w);
                uint32_t l01 = packbf(f.x - bfround(f.x), f.y - bfround(f.y));
                uint32_t l23 = packbf(f.z - bfround(f.z), f.w - bfround(f.w));
                char* dst = smem + OFF_V + kk * VSTRB + 2 * d0;
                *(uint2*)dst = make_uint2(h01, h23);
                *(uint2*)(dst + 36864) = make_uint2(l01, l23);
            }
        }
        __syncthreads();

        #pragma unroll
        for (int ks = 0; ks < 4; ++ks) {
            // V b-frags via ldmatrix.trans from natural [k][d] layout (hi+lo hybrid)
            uint32_t vb[4][4];
            #pragma unroll
            for (int nj = 0; nj < 4; ++nj) {
                uint32_t rbv = sb + OFF_V
                    + (p3kg * 64 + 16 * ks + lr8 + 8 * lg) * VSTRB
                    + 2 * (32 * p3nh + 8 * nj) + 36864 * kg4;
                ldm_x4t(vb[nj], rbv);
            }
            uint32_t koffB = 2u * (half * 256 + p3kg * 64 + 16 * ks);
            #pragma unroll
            for (int mt = 0; mt < 2; ++mt) {
                uint32_t ah[4], al[4];
                uint32_t ra = sb + (32 * p3mh + 16 * mt + lr8 + 8 * lg) * WROWB
                              + koffB + 16 * kg4;
                ldm_x4(ah, ra);
                ldm_x4(al, ra + 1040);
                #pragma unroll
                for (int nj = 0; nj < 4; ++nj) {
                    mma_bf16(accO[mt][nj], ah, vb[nj]);
                    mma_bf16(accO[mt][nj], al, vb[nj]);
                    mma_bf16(accO[mt][nj], ah, vb[nj] + 2);
                }
            }
        }
    }

    // ---- reduce 4 kg partials ----
    #pragma unroll
    for (int r = 0; r < 4; ++r) {
        __syncthreads();
        if (p3kg == r) {
            #pragma unroll
            for (int mt = 0; mt < 2; ++mt)
                #pragma unroll
                for (int nj = 0; nj < 4; ++nj) {
                    int row = 32 * p3mh + 16 * mt + lr;
                    int col = 32 * p3nh + 8 * nj + 2 * lc;
                    float2* p0 = (float2*)(sRed + row * RSTR + col);
                    float2* p1 = (float2*)(sRed + (row + 8) * RSTR + col);
                    if (r == 0) {
                        *p0 = make_float2(accO[mt][nj][0], accO[mt][nj][1]);
                        *p1 = make_float2(accO[mt][nj][2], accO[mt][nj][3]);
                    } else {
                        float2 a = *p0, bq = *p1;
                        a.x += accO[mt][nj][0]; a.y += accO[mt][nj][1];
                        bq.x += accO[mt][nj][2]; bq.y += accO[mt][nj][3];
                        *p0 = a; *p1 = bq;
                    }
                }
        }
    }
    __syncthreads();

    // ---- write out ----
    #pragma unroll
    for (int t = 0; t < 2; ++t) {
        int idx = tid + 512 * t;
        int row = idx >> 4, c0 = (idx & 15) << 2;
        float4 o = *(float4*)(sRed + row * RSTR + c0);
        *(float4*)(Op + row * DDIM + c0) = o;
    }
}

extern "C" void kernel_launch(void* const* d_in, const int* in_sizes, int n_in,
                              void* d_out, int out_size)
{
    const float* Q    = (const float*)d_in[0];
    const float* K    = (const float*)d_in[1];
    const float* V    = (const float*)d_in[2];
    const float* mask = (const float*)d_in[3];
    const float* adj  = (const float*)d_in[4];
    const float* dist = (const float*)d_in[5];

    float* outp  = (float*)d_out;
    float* pattn = outp + (size_t)BB * HH * SDIM * DDIM;

    precompute_C_kernel<<<BB * SDIM, 256>>>(adj, dist, mask);

    cudaFuncSetAttribute(attn_mma_kernel,
                         cudaFuncAttributeMaxDynamicSharedMemorySize, SMEM_BYTES);
    dim3 grid(NKT, HH, BB);
    attn_mma_kernel<<<grid, THREADS, SMEM_BYTES>>>(Q, K, V, mask, outp, pattn);
}

// round 8
// speedup vs baseline: 4.2851x; 1.1056x over previous
#include <cuda_runtime.h>
#include <cuda_bf16.h>
#include <math_constants.h>
#include <cstdint>

#define BB 16
#define HH 16
#define SDIM 512
#define DDIM 64
#define QT 64
#define THREADS 512
#define KSTRB 144

#define L_ATT 0.33f
#define L_DIST 0.33f
#define L_ADJ (1.0f - 0.33f - 0.33f)

// ---- smem map (bytes) ----
#define OFF_QS   0                    // Q hi 64x144, lo at +9216
#define OFF_K    18432                // 2 bufs x (hi 9216 + lo 9216)
#define OFF_V    55296                // V hi 512x144
#define OFF_VLO  129024               // V lo
#define OFF_RED  202752               // 64 x 68 f32
#define RSTR     68
#define OFF_RM   220160               // rowmax 64x4 f32
#define OFF_RS   221184               // rowsum 64x4 f32
#define OFF_MASK 222208               // 512 f32
#define SMEM_BYTES 224256

__device__ float g_C[(size_t)BB * SDIM * SDIM];

__global__ __launch_bounds__(256) void precompute_C_kernel(
    const float* __restrict__ adj, const float* __restrict__ dist,
    const float* __restrict__ mask)
{
    int row = blockIdx.x;
    int b = row >> 9;
    const float* arow = adj  + (size_t)row * SDIM;
    const float* drow = dist + (size_t)row * SDIM;
    const float* mrow = mask + (size_t)b * SDIM;
    float* crow = g_C + (size_t)row * SDIM;
    int tid = threadIdx.x, w = tid >> 5, l = tid & 31;

    float a0 = arow[tid], a1 = arow[tid + 256];
    float d0 = drow[tid], d1 = drow[tid + 256];
    float m0 = mrow[tid], m1 = mrow[tid + 256];
    float x0 = (m0 == 0.0f) ? -CUDART_INF_F : -d0;
    float x1 = (m1 == 0.0f) ? -CUDART_INF_F : -d1;

    float asum = a0 + a1, xmax = fmaxf(x0, x1);
    #pragma unroll
    for (int o = 16; o > 0; o >>= 1) {
        asum += __shfl_xor_sync(0xffffffffu, asum, o);
        xmax = fmaxf(xmax, __shfl_xor_sync(0xffffffffu, xmax, o));
    }
    __shared__ float rs[8], rm[8], re[8];
    if (l == 0) { rs[w] = asum; rm[w] = xmax; }
    __syncthreads();
    float ts = 0.0f, tm = -CUDART_INF_F;
    #pragma unroll
    for (int i = 0; i < 8; i++) { ts += rs[i]; tm = fmaxf(tm, rm[i]); }

    float e0 = __expf(x0 - tm), e1 = __expf(x1 - tm), es = e0 + e1;
    #pragma unroll
    for (int o = 16; o > 0; o >>= 1) es += __shfl_xor_sync(0xffffffffu, es, o);
    if (l == 0) re[w] = es;
    __syncthreads();
    float te = 0.0f;
    #pragma unroll
    for (int i = 0; i < 8; i++) te += re[i];

    float inv_a = 1.0f / (ts + 1e-6f), inv_e = 1.0f / te;
    crow[tid]       = L_DIST * e0 * inv_e + L_ADJ * a0 * inv_a;
    crow[tid + 256] = L_DIST * e1 * inv_e + L_ADJ * a1 * inv_a;
}

__device__ __forceinline__ void mma_bf16(float* c, const uint32_t* a, const uint32_t* b) {
    asm volatile("mma.sync.aligned.m16n8k16.row.col.f32.bf16.bf16.f32 "
        "{%0,%1,%2,%3}, {%4,%5,%6,%7}, {%8,%9}, {%0,%1,%2,%3};"
        : "+f"(c[0]), "+f"(c[1]), "+f"(c[2]), "+f"(c[3])
        : "r"(a[0]), "r"(a[1]), "r"(a[2]), "r"(a[3]), "r"(b[0]), "r"(b[1]));
}
__device__ __forceinline__ void ldm_x4(uint32_t* r, uint32_t a) {
    asm volatile("ldmatrix.sync.aligned.m8n8.x4.shared.b16 {%0,%1,%2,%3}, [%4];"
        : "=r"(r[0]), "=r"(r[1]), "=r"(r[2]), "=r"(r[3]) : "r"(a));
}
__device__ __forceinline__ void ldm_x4t(uint32_t* r, uint32_t a) {
    asm volatile("ldmatrix.sync.aligned.m8n8.x4.trans.shared.b16 {%0,%1,%2,%3}, [%4];"
        : "=r"(r[0]), "=r"(r[1]), "=r"(r[2]), "=r"(r[3]) : "r"(a));
}
__device__ __forceinline__ uint32_t smem_u32(const void* p) {
    uint32_t a;
    asm("{ .reg .u64 t; cvta.to.shared.u64 t, %1; cvt.u32.u64 %0, t; }" : "=r"(a) : "l"(p));
    return a;
}
__device__ __forceinline__ uint32_t packbf(float lo, float hi) {
    uint32_t r;
    asm("cvt.rn.bf16x2.f32 %0, %1, %2;" : "=r"(r) : "f"(hi), "f"(lo));
    return r;
}
__device__ __forceinline__ float bfround(float x) {
    return __bfloat162float(__float2bfloat16_rn(x));
}

__global__ __launch_bounds__(512) void attn_mma_kernel(
    const float* __restrict__ Q, const float* __restrict__ K,
    const float* __restrict__ V, const float* __restrict__ mask,
    float* __restrict__ Og, float* __restrict__ Pg)
{
    extern __shared__ char smem[];
    uint32_t sb = smem_u32(smem);
    float* sMask = (float*)(smem + OFF_MASK);
    float* sRed = (float*)(smem + OFF_RED);

    int tid = threadIdx.x;
    int wid = tid >> 5, l = tid & 31;
    int lr = l >> 2, lc = l & 3;
    int lr8 = l & 7, lg = (l >> 3) & 1, kg4 = l >> 4;
    int wm = wid >> 2, wn = wid & 3;

    int qt = blockIdx.x, h = blockIdx.y, b = blockIdx.z;
    int q0 = qt * QT;
    size_t bh_ = (size_t)b * HH + h;
    const float* Qp = Q + (bh_ * SDIM + q0) * DDIM;
    const float* Kp = K + bh_ * SDIM * DDIM;
    const float* Vp = V + bh_ * SDIM * DDIM;
    const float* Mp = mask + (size_t)b * SDIM;
    const float* Cp = g_C + ((size_t)b * SDIM + q0) * SDIM;
    float* Op = Og + (bh_ * SDIM + q0) * DDIM;
    float* Pp = Pg + (bh_ * SDIM + q0) * SDIM;

    sMask[tid] = Mp[tid];

    // ---- Q (x 1/8) -> hi/lo bf16 smem ----
    {
        const float4* Q4 = (const float4*)Qp;
        #pragma unroll
        for (int t = 0; t < 2; ++t) {
            int idx = tid + 512 * t;
            float4 f = Q4[idx];
            int r = idx >> 4, c = (idx & 15) << 2;
            float v0 = f.x * 0.125f, v1 = f.y * 0.125f, v2 = f.z * 0.125f, v3 = f.w * 0.125f;
            char* dst = smem + OFF_QS + r * KSTRB + 2 * c;
            *(uint2*)dst = make_uint2(packbf(v0, v1), packbf(v2, v3));
            *(uint2*)(dst + 9216) = make_uint2(
                packbf(v0 - bfround(v0), v1 - bfround(v1)),
                packbf(v2 - bfround(v2), v3 - bfround(v3)));
        }
    }
    // ---- K tile 0 -> buf0; prefetch tile 1 ----
    {
        const float4* K4 = (const float4*)Kp;
        #pragma unroll
        for (int t = 0; t < 2; ++t) {
            int idx = tid + 512 * t;
            float4 f = K4[idx];
            int r = idx >> 4, c = (idx & 15) << 2;
            char* dst = smem + OFF_K + r * KSTRB + 2 * c;
            *(uint2*)dst = make_uint2(packbf(f.x, f.y), packbf(f.z, f.w));
            *(uint2*)(dst + 9216) = make_uint2(
                packbf(f.x - bfround(f.x), f.y - bfround(f.y)),
                packbf(f.z - bfround(f.z), f.w - bfround(f.w)));
        }
    }
    float4 pf[2];
    {
        const float4* K4 = (const float4*)(Kp + 4096);
        pf[0] = K4[tid]; pf[1] = K4[tid + 512];
    }
    __syncthreads();

    // ---- resident Q fragments, rows 16*wm ----
    uint32_t qah[4][4], qal[4][4];
    {
        uint32_t ra = sb + OFF_QS + (16 * wm + lr8 + 8 * lg) * KSTRB + 16 * kg4;
        #pragma unroll
        for (int ks = 0; ks < 4; ++ks) {
            ldm_x4(qah[ks], ra + ks * 32);
            ldm_x4(qal[ks], ra + 9216 + ks * 32);
        }
    }

    // ---- Phase 1: scores (regs), 8 tiles, double-buffered K ----
    float sc[8][2][4];
    #pragma unroll
    for (int kt = 0; kt < 8; ++kt) {
        #pragma unroll
        for (int nf = 0; nf < 2; ++nf)
            #pragma unroll
            for (int e = 0; e < 4; ++e) sc[kt][nf][e] = 0.0f;

        uint32_t kb = sb + OFF_K + (kt & 1) * 18432;
        #pragma unroll
        for (int ks = 0; ks < 4; ++ks) {
            uint32_t bh[4], bl[4];
            uint32_t rb = kb + (16 * wn + lr8 + 8 * kg4) * KSTRB + 16 * lg + 32 * ks;
            ldm_x4(bh, rb);
            ldm_x4(bl, rb + 9216);
            #pragma unroll
            for (int nf = 0; nf < 2; ++nf) {
                mma_bf16(sc[kt][nf], qah[ks], bh + 2 * nf);
                mma_bf16(sc[kt][nf], qal[ks], bh + 2 * nf);
                mma_bf16(sc[kt][nf], qah[ks], bl + 2 * nf);
            }
        }
        if (kt < 7) {
            // store prefetched tile kt+1
            #pragma unroll
            for (int t = 0; t < 2; ++t) {
                int idx = tid + 512 * t;
                float4 f = pf[t];
                int r = idx >> 4, c = (idx & 15) << 2;
                char* dst = smem + OFF_K + ((kt + 1) & 1) * 18432 + r * KSTRB + 2 * c;
                *(uint2*)dst = make_uint2(packbf(f.x, f.y), packbf(f.z, f.w));
                *(uint2*)(dst + 9216) = make_uint2(
                    packbf(f.x - bfround(f.x), f.y - bfround(f.y)),
                    packbf(f.z - bfround(f.z), f.w - bfround(f.w)));
            }
            __syncthreads();
            if (kt < 6) {
                const float4* K4 = (const float4*)(Kp + (size_t)(kt + 2) * 4096);
                pf[0] = K4[tid]; pf[1] = K4[tid + 512];
            }
        }
    }

    // ---- stage V (full 512x64) hi/lo ----
    {
        const float4* V4 = (const float4*)Vp;
        #pragma unroll
        for (int t = 0; t < 16; ++t) {
            int idx = tid + 512 * t;
            float4 f = V4[idx];
            int r = idx >> 4, c = (idx & 15) << 2;
            char* dst = smem + OFF_V + r * KSTRB + 2 * c;
            *(uint2*)dst = make_uint2(packbf(f.x, f.y), packbf(f.z, f.w));
            *(uint2*)(dst + 73728) = make_uint2(
                packbf(f.x - bfround(f.x), f.y - bfround(f.y)),
                packbf(f.z - bfround(f.z), f.w - bfround(f.w)));
        }
    }

    // ---- Phase 2: softmax in registers ----
    int r0 = 16 * wm + lr, r1 = r0 + 8;
    float2 mk[8][2];
    #pragma unroll
    for (int j = 0; j < 8; ++j)
        #pragma unroll
        for (int nf = 0; nf < 2; ++nf)
            mk[j][nf] = *(float2*)(smem + OFF_MASK + 4 * (64 * j + 16 * wn + 8 * nf + 2 * lc));

    float mx0 = -CUDART_INF_F, mx1 = -CUDART_INF_F;
    #pragma unroll
    for (int j = 0; j < 8; ++j)
        #pragma unroll
        for (int nf = 0; nf < 2; ++nf) {
            if (mk[j][nf].x == 0.0f) { sc[j][nf][0] = -1e12f; sc[j][nf][2] = -1e12f; }
            if (mk[j][nf].y == 0.0f) { sc[j][nf][1] = -1e12f; sc[j][nf][3] = -1e12f; }
            mx0 = fmaxf(mx0, fmaxf(sc[j][nf][0], sc[j][nf][1]));
            mx1 = fmaxf(mx1, fmaxf(sc[j][nf][2], sc[j][nf][3]));
        }
    #pragma unroll
    for (int o = 1; o < 4; o <<= 1) {
        mx0 = fmaxf(mx0, __shfl_xor_sync(0xffffffffu, mx0, o));
        mx1 = fmaxf(mx1, __shfl_xor_sync(0xffffffffu, mx1, o));
    }
    if (lc == 0) {
        ((float*)(smem + OFF_RM))[r0 * 4 + wn] = mx0;
        ((float*)(smem + OFF_RM))[r1 * 4 + wn] = mx1;
    }
    __syncthreads();
    {
        float4 m0 = *(float4*)(smem + OFF_RM + r0 * 16);
        float4 m1 = *(float4*)(smem + OFF_RM + r1 * 16);
        mx0 = fmaxf(fmaxf(m0.x, m0.y), fmaxf(m0.z, m0.w));
        mx1 = fmaxf(fmaxf(m1.x, m1.y), fmaxf(m1.z, m1.w));
    }
    float s0 = 0.0f, s1 = 0.0f;
    #pragma unroll
    for (int j = 0; j < 8; ++j)
        #pragma unroll
        for (int nf = 0; nf < 2; ++nf) {
            sc[j][nf][0] = __expf(sc[j][nf][0] - mx0);
            sc[j][nf][1] = __expf(sc[j][nf][1] - mx0);
            sc[j][nf][2] = __expf(sc[j][nf][2] - mx1);
            sc[j][nf][3] = __expf(sc[j][nf][3] - mx1);
            s0 += sc[j][nf][0] + sc[j][nf][1];
            s1 += sc[j][nf][2] + sc[j][nf][3];
        }
    #pragma unroll
    for (int o = 1; o < 4; o <<= 1) {
        s0 += __shfl_xor_sync(0xffffffffu, s0, o);
        s1 += __shfl_xor_sync(0xffffffffu, s1, o);
    }
    if (lc == 0) {
        ((float*)(smem + OFF_RS))[r0 * 4 + wn] = s0;
        ((float*)(smem + OFF_RS))[r1 * 4 + wn] = s1;
    }
    __syncthreads();
    float inv0, inv1;
    {
        float4 t0 = *(float4*)(smem + OFF_RS + r0 * 16);
        float4 t1 = *(float4*)(smem + OFF_RS + r1 * 16);
        inv0 = 1.0f / (t0.x + t0.y + t0.z + t0.w);
        inv1 = 1.0f / (t1.x + t1.y + t1.z + t1.w);
    }

    // ---- normalize, store p_attn, blend with C, pack W A-frags ----
    uint32_t wah[8][4], wal[8][4];
    #pragma unroll
    for (int j = 0; j < 8; ++j)
        #pragma unroll
        for (int nf = 0; nf < 2; ++nf) {
            int col = 64 * j + 16 * wn + 8 * nf + 2 * lc;
            float p00 = sc[j][nf][0] * inv0, p01 = sc[j][nf][1] * inv0;
            float p10 = sc[j][nf][2] * inv1, p11 = sc[j][nf][3] * inv1;
            __stcs((float2*)(Pp + (size_t)r0 * SDIM + col), make_float2(p00, p01));
            __stcs((float2*)(Pp + (size_t)r1 * SDIM + col), make_float2(p10, p11));
            float2 c0 = __ldg((const float2*)(Cp + (size_t)r0 * SDIM + col));
            float2 c1 = __ldg((const float2*)(Cp + (size_t)r1 * SDIM + col));
            float w00 = fmaf(L_ATT, p00, c0.x), w01 = fmaf(L_ATT, p01, c0.y);
            float w10 = fmaf(L_ATT, p10, c1.x), w11 = fmaf(L_ATT, p11, c1.y);
            wah[j][2 * nf]     = packbf(w00, w01);
            wah[j][2 * nf + 1] = packbf(w10, w11);
            wal[j][2 * nf]     = packbf(w00 - bfround(w00), w01 - bfround(w01));
            wal[j][2 * nf + 1] = packbf(w10 - bfround(w10), w11 - bfround(w11));
        }

    // ---- Phase 3: out partials (no barriers; V resident, W in regs) ----
    float accO[8][4];
    #pragma unroll
    for (int nj = 0; nj < 8; ++nj)
        #pragma unroll
        for (int e = 0; e < 4; ++e) accO[nj][e] = 0.0f;

    #pragma unroll
    for (int j = 0; j < 8; ++j) {
        uint32_t vrow = sb + OFF_V + (64 * j + 16 * wn + lr8 + 8 * lg) * KSTRB + 73728 * kg4;
        #pragma unroll
        for (int nj = 0; nj < 8; ++nj) {
            uint32_t vb[4];
            ldm_x4t(vb, vrow + 16 * nj);
            mma_bf16(accO[nj], wah[j], vb);
            mma_bf16(accO[nj], wal[j], vb);
            mma_bf16(accO[nj], wah[j], vb + 2);
        }
    }

    // ---- reduce 4 wn partials ----
    #pragma unroll
    for (int r = 0; r < 4; ++r) {
        __syncthreads();
        if (wn == r) {
            #pragma unroll
            for (int nj = 0; nj < 8; ++nj) {
                int col = 8 * nj + 2 * lc;
                float2* p0 = (float2*)(sRed + r0 * RSTR + col);
                float2* p1 = (float2*)(sRed + r1 * RSTR + col);
                if (r == 0) {
                    *p0 = make_float2(accO[nj][0], accO[nj][1]);
                    *p1 = make_float2(accO[nj][2], accO[nj][3]);
                } else {
                    float2 a = *p0, bq = *p1;
                    a.x += accO[nj][0]; a.y += accO[nj][1];
                    bq.x += accO[nj][2]; bq.y += accO[nj][3];
                    *p0 = a; *p1 = bq;
                }
            }
        }
    }
    __syncthreads();

    #pragma unroll
    for (int t = 0; t < 2; ++t) {
        int idx = tid + 512 * t;
        int row = idx >> 4, c0 = (idx & 15) << 2;
        *(float4*)(Op + row * DDIM + c0) = *(float4*)(sRed + row * RSTR + c0);
    }
}

extern "C" void kernel_launch(void* const* d_in, const int* in_sizes, int n_in,
                              void* d_out, int out_size)
{
    const float* Q    = (const float*)d_in[0];
    const float* K    = (const float*)d_in[1];
    const float* V    = (const float*)d_in[2];
    const float* mask = (const float*)d_in[3];
    const float* adj  = (const float*)d_in[4];
    const float* dist = (const float*)d_in[5];

    float* outp  = (float*)d_out;
    float* pattn = outp + (size_t)BB * HH * SDIM * DDIM;

    precompute_C_kernel<<<BB * SDIM, 256>>>(adj, dist, mask);

    cudaFuncSetAttribute(attn_mma_kernel,
                         cudaFuncAttributeMaxDynamicSharedMemorySize, SMEM_BYTES);
    dim3 grid(SDIM / QT, HH, BB);
    attn_mma_kernel<<<grid, THREADS, SMEM_BYTES>>>(Q, K, V, mask, outp, pattn);
}

// round 9
// speedup vs baseline: 4.4170x; 1.0308x over previous
#include <cuda_runtime.h>
#include <cuda_bf16.h>
#include <math_constants.h>
#include <cstdint>

#define BB 16
#define HH 16
#define SDIM 512
#define DDIM 64
#define QT 64
#define THREADS 512
#define KSTRB 144

#define L_ATT 0.33f
#define L_DIST 0.33f
#define L_ADJ (1.0f - 0.33f - 0.33f)

// ---- smem map (bytes) ----
#define OFF_QS   0
#define OFF_K    18432
#define OFF_V    55296
#define OFF_RED  202752
#define RSTR     68
#define OFF_RM   220160
#define OFF_RS   221184
#define OFF_MASK 222208
#define SMEM_BYTES 224256

__device__ float g_C[(size_t)BB * SDIM * SDIM];

__global__ __launch_bounds__(256) void precompute_C_kernel(
    const float* __restrict__ adj, const float* __restrict__ dist,
    const float* __restrict__ mask)
{
    int row = blockIdx.x;
    int b = row >> 9;
    const float* arow = adj  + (size_t)row * SDIM;
    const float* drow = dist + (size_t)row * SDIM;
    const float* mrow = mask + (size_t)b * SDIM;
    float* crow = g_C + (size_t)row * SDIM;
    int tid = threadIdx.x, w = tid >> 5, l = tid & 31;

    float a0 = arow[tid], a1 = arow[tid + 256];
    float d0 = drow[tid], d1 = drow[tid + 256];
    float m0 = mrow[tid], m1 = mrow[tid + 256];
    float x0 = (m0 == 0.0f) ? -CUDART_INF_F : -d0;
    float x1 = (m1 == 0.0f) ? -CUDART_INF_F : -d1;

    float asum = a0 + a1, xmax = fmaxf(x0, x1);
    #pragma unroll
    for (int o = 16; o > 0; o >>= 1) {
        asum += __shfl_xor_sync(0xffffffffu, asum, o);
        xmax = fmaxf(xmax, __shfl_xor_sync(0xffffffffu, xmax, o));
    }
    __shared__ float rs[8], rm[8], re[8];
    if (l == 0) { rs[w] = asum; rm[w] = xmax; }
    __syncthreads();
    float ts = 0.0f, tm = -CUDART_INF_F;
    #pragma unroll
    for (int i = 0; i < 8; i++) { ts += rs[i]; tm = fmaxf(tm, rm[i]); }

    float e0 = __expf(x0 - tm), e1 = __expf(x1 - tm), es = e0 + e1;
    #pragma unroll
    for (int o = 16; o > 0; o >>= 1) es += __shfl_xor_sync(0xffffffffu, es, o);
    if (l == 0) re[w] = es;
    __syncthreads();
    float te = 0.0f;
    #pragma unroll
    for (int i = 0; i < 8; i++) te += re[i];

    float inv_a = 1.0f / (ts + 1e-6f), inv_e = 1.0f / te;
    crow[tid]       = L_DIST * e0 * inv_e + L_ADJ * a0 * inv_a;
    crow[tid + 256] = L_DIST * e1 * inv_e + L_ADJ * a1 * inv_a;
}

__device__ __forceinline__ void mma_bf16(float* c, const uint32_t* a, const uint32_t* b) {
    asm volatile("mma.sync.aligned.m16n8k16.row.col.f32.bf16.bf16.f32 "
        "{%0,%1,%2,%3}, {%4,%5,%6,%7}, {%8,%9}, {%0,%1,%2,%3};"
        : "+f"(c[0]), "+f"(c[1]), "+f"(c[2]), "+f"(c[3])
        : "r"(a[0]), "r"(a[1]), "r"(a[2]), "r"(a[3]), "r"(b[0]), "r"(b[1]));
}
__device__ __forceinline__ void ldm_x4(uint32_t* r, uint32_t a) {
    asm volatile("ldmatrix.sync.aligned.m8n8.x4.shared.b16 {%0,%1,%2,%3}, [%4];"
        : "=r"(r[0]), "=r"(r[1]), "=r"(r[2]), "=r"(r[3]) : "r"(a));
}
__device__ __forceinline__ void ldm_x4t(uint32_t* r, uint32_t a) {
    asm volatile("ldmatrix.sync.aligned.m8n8.x4.trans.shared.b16 {%0,%1,%2,%3}, [%4];"
        : "=r"(r[0]), "=r"(r[1]), "=r"(r[2]), "=r"(r[3]) : "r"(a));
}
__device__ __forceinline__ uint32_t smem_u32(const void* p) {
    uint32_t a;
    asm("{ .reg .u64 t; cvta.to.shared.u64 t, %1; cvt.u32.u64 %0, t; }" : "=r"(a) : "l"(p));
    return a;
}
__device__ __forceinline__ uint32_t packbf(float lo, float hi) {
    uint32_t r;
    asm("cvt.rn.bf16x2.f32 %0, %1, %2;" : "=r"(r) : "f"(hi), "f"(lo));
    return r;
}
__device__ __forceinline__ float bfround(float x) {
    return __bfloat162float(__float2bfloat16_rn(x));
}

__global__ __launch_bounds__(512) void attn_mma_kernel(
    const float* __restrict__ Q, const float* __restrict__ K,
    const float* __restrict__ V, const float* __restrict__ mask,
    float* __restrict__ Og, float* __restrict__ Pg)
{
    extern __shared__ char smem[];
    uint32_t sb = smem_u32(smem);
    float* sMask = (float*)(smem + OFF_MASK);
    float* sRed = (float*)(smem + OFF_RED);

    int tid = threadIdx.x;
    int wid = tid >> 5, l = tid & 31;
    int lr = l >> 2, lc = l & 3;
    int lr8 = l & 7, lg = (l >> 3) & 1, kg4 = l >> 4;
    int wm = wid >> 2, wn = wid & 3;

    int qt = blockIdx.x, h = blockIdx.y, b = blockIdx.z;
    int q0 = qt * QT;
    size_t bh_ = (size_t)b * HH + h;
    const float* Qp = Q + (bh_ * SDIM + q0) * DDIM;
    const float* Kp = K + bh_ * SDIM * DDIM;
    const float* Vp = V + bh_ * SDIM * DDIM;
    const float* Mp = mask + (size_t)b * SDIM;
    const float* Cp = g_C + ((size_t)b * SDIM + q0) * SDIM;
    float* Op = Og + (bh_ * SDIM + q0) * DDIM;
    float* Pp = Pg + (bh_ * SDIM + q0) * SDIM;

    sMask[tid] = Mp[tid];

    // ---- Q (x 1/8) -> hi/lo bf16 smem ----
    {
        const float4* Q4 = (const float4*)Qp;
        #pragma unroll
        for (int t = 0; t < 2; ++t) {
            int idx = tid + 512 * t;
            float4 f = Q4[idx];
            int r = idx >> 4, c = (idx & 15) << 2;
            float v0 = f.x * 0.125f, v1 = f.y * 0.125f, v2 = f.z * 0.125f, v3 = f.w * 0.125f;
            char* dst = smem + OFF_QS + r * KSTRB + 2 * c;
            *(uint2*)dst = make_uint2(packbf(v0, v1), packbf(v2, v3));
            *(uint2*)(dst + 9216) = make_uint2(
                packbf(v0 - bfround(v0), v1 - bfround(v1)),
                packbf(v2 - bfround(v2), v3 - bfround(v3)));
        }
    }
    // ---- K tile 0 -> buf0; prefetch tile 1 ----
    {
        const float4* K4 = (const float4*)Kp;
        #pragma unroll
        for (int t = 0; t < 2; ++t) {
            int idx = tid + 512 * t;
            float4 f = K4[idx];
            int r = idx >> 4, c = (idx & 15) << 2;
            char* dst = smem + OFF_K + r * KSTRB + 2 * c;
            *(uint2*)dst = make_uint2(packbf(f.x, f.y), packbf(f.z, f.w));
            *(uint2*)(dst + 9216) = make_uint2(
                packbf(f.x - bfround(f.x), f.y - bfround(f.y)),
                packbf(f.z - bfround(f.z), f.w - bfround(f.w)));
        }
    }
    float4 pf[2];
    {
        const float4* K4 = (const float4*)(Kp + 4096);
        pf[0] = K4[tid]; pf[1] = K4[tid + 512];
    }
    __syncthreads();

    // ---- resident Q fragments ----
    uint32_t qah[4][4], qal[4][4];
    {
        uint32_t ra = sb + OFF_QS + (16 * wm + lr8 + 8 * lg) * KSTRB + 16 * kg4;
        #pragma unroll
        for (int ks = 0; ks < 4; ++ks) {
            ldm_x4(qah[ks], ra + ks * 32);
            ldm_x4(qal[ks], ra + 9216 + ks * 32);
        }
    }

    // ---- Phase 1: scores (regs), double-buffered K, pipelined B-frags ----
    float sc[8][2][4];
    #pragma unroll
    for (int kt = 0; kt < 8; ++kt) {
        #pragma unroll
        for (int nf = 0; nf < 2; ++nf)
            #pragma unroll
            for (int e = 0; e < 4; ++e) sc[kt][nf][e] = 0.0f;

        uint32_t rbase = sb + OFF_K + (kt & 1) * 18432
                         + (16 * wn + lr8 + 8 * kg4) * KSTRB + 16 * lg;
        uint32_t bh[2][4];
        ldm_x4(bh[0], rbase);
        #pragma unroll
        for (int ks = 0; ks < 4; ++ks) {
            int cc = ks & 1;
            if (ks < 3) ldm_x4(bh[cc ^ 1], rbase + 32 * (ks + 1));
            uint32_t bl[4];
            ldm_x4(bl, rbase + 9216 + 32 * ks);
            #pragma unroll
            for (int nf = 0; nf < 2; ++nf) {
                mma_bf16(sc[kt][nf], qah[ks], bh[cc] + 2 * nf);
                mma_bf16(sc[kt][nf], qal[ks], bh[cc] + 2 * nf);
                mma_bf16(sc[kt][nf], qah[ks], bl + 2 * nf);
            }
        }
        if (kt < 7) {
            #pragma unroll
            for (int t = 0; t < 2; ++t) {
                int idx = tid + 512 * t;
                float4 f = pf[t];
                int r = idx >> 4, c = (idx & 15) << 2;
                char* dst = smem + OFF_K + ((kt + 1) & 1) * 18432 + r * KSTRB + 2 * c;
                *(uint2*)dst = make_uint2(packbf(f.x, f.y), packbf(f.z, f.w));
                *(uint2*)(dst + 9216) = make_uint2(
                    packbf(f.x - bfround(f.x), f.y - bfround(f.y)),
                    packbf(f.z - bfround(f.z), f.w - bfround(f.w)));
            }
            __syncthreads();
            if (kt < 6) {
                const float4* K4 = (const float4*)(Kp + (size_t)(kt + 2) * 4096);
                pf[0] = K4[tid]; pf[1] = K4[tid + 512];
            }
        }
    }

    // ---- stage V (full 512x64) hi/lo ----
    {
        const float4* V4 = (const float4*)Vp;
        #pragma unroll
        for (int t = 0; t < 16; ++t) {
            int idx = tid + 512 * t;
            float4 f = V4[idx];
            int r = idx >> 4, c = (idx & 15) << 2;
            char* dst = smem + OFF_V + r * KSTRB + 2 * c;
            *(uint2*)dst = make_uint2(packbf(f.x, f.y), packbf(f.z, f.w));
            *(uint2*)(dst + 73728) = make_uint2(
                packbf(f.x - bfround(f.x), f.y - bfround(f.y)),
                packbf(f.z - bfround(f.z), f.w - bfround(f.w)));
        }
    }

    // ---- softmax reductions (scores stay in regs) ----
    int r0 = 16 * wm + lr, r1 = r0 + 8;
    {
        float2 mk;
        #pragma unroll
        for (int j = 0; j < 8; ++j)
            #pragma unroll
            for (int nf = 0; nf < 2; ++nf) {
                mk = *(float2*)(smem + OFF_MASK + 4 * (64 * j + 16 * wn + 8 * nf + 2 * lc));
                if (mk.x == 0.0f) { sc[j][nf][0] = -1e12f; sc[j][nf][2] = -1e12f; }
                if (mk.y == 0.0f) { sc[j][nf][1] = -1e12f; sc[j][nf][3] = -1e12f; }
            }
    }
    float mx0 = -CUDART_INF_F, mx1 = -CUDART_INF_F;
    #pragma unroll
    for (int j = 0; j < 8; ++j)
        #pragma unroll
        for (int nf = 0; nf < 2; ++nf) {
            mx0 = fmaxf(mx0, fmaxf(sc[j][nf][0], sc[j][nf][1]));
            mx1 = fmaxf(mx1, fmaxf(sc[j][nf][2], sc[j][nf][3]));
        }
    #pragma unroll
    for (int o = 1; o < 4; o <<= 1) {
        mx0 = fmaxf(mx0, __shfl_xor_sync(0xffffffffu, mx0, o));
        mx1 = fmaxf(mx1, __shfl_xor_sync(0xffffffffu, mx1, o));
    }
    if (lc == 0) {
        ((float*)(smem + OFF_RM))[r0 * 4 + wn] = mx0;
        ((float*)(smem + OFF_RM))[r1 * 4 + wn] = mx1;
    }
    __syncthreads();
    {
        float4 m0 = *(float4*)(smem + OFF_RM + r0 * 16);
        float4 m1 = *(float4*)(smem + OFF_RM + r1 * 16);
        mx0 = fmaxf(fmaxf(m0.x, m0.y), fmaxf(m0.z, m0.w));
        mx1 = fmaxf(fmaxf(m1.x, m1.y), fmaxf(m1.z, m1.w));
    }
    float s0 = 0.0f, s1 = 0.0f;
    #pragma unroll
    for (int j = 0; j < 8; ++j)
        #pragma unroll
        for (int nf = 0; nf < 2; ++nf) {
            sc[j][nf][0] = __expf(sc[j][nf][0] - mx0);
            sc[j][nf][1] = __expf(sc[j][nf][1] - mx0);
            sc[j][nf][2] = __expf(sc[j][nf][2] - mx1);
            sc[j][nf][3] = __expf(sc[j][nf][3] - mx1);
            s0 += sc[j][nf][0] + sc[j][nf][1];
            s1 += sc[j][nf][2] + sc[j][nf][3];
        }
    #pragma unroll
    for (int o = 1; o < 4; o <<= 1) {
        s0 += __shfl_xor_sync(0xffffffffu, s0, o);
        s1 += __shfl_xor_sync(0xffffffffu, s1, o);
    }
    if (lc == 0) {
        ((float*)(smem + OFF_RS))[r0 * 4 + wn] = s0;
        ((float*)(smem + OFF_RS))[r1 * 4 + wn] = s1;
    }
    __syncthreads();
    float inv0, inv1;
    {
        float4 t0 = *(float4*)(smem + OFF_RS + r0 * 16);
        float4 t1 = *(float4*)(smem + OFF_RS + r1 * 16);
        inv0 = 1.0f / (t0.x + t0.y + t0.z + t0.w);
        inv1 = 1.0f / (t1.x + t1.y + t1.z + t1.w);
    }

    // ---- fused phase 2+3 per 64-key chunk j, C prefetched, V frags pipelined ----
    float accO[8][4];
    #pragma unroll
    for (int nj = 0; nj < 8; ++nj)
        #pragma unroll
        for (int e = 0; e < 4; ++e) accO[nj][e] = 0.0f;

    int colb = 16 * wn + 2 * lc;
    float2 cb[2][2][2];
    #pragma unroll
    for (int nf = 0; nf < 2; ++nf) {
        cb[0][0][nf] = __ldg((const float2*)(Cp + (size_t)r0 * SDIM + colb + 8 * nf));
        cb[0][1][nf] = __ldg((const float2*)(Cp + (size_t)r1 * SDIM + colb + 8 * nf));
    }

    #pragma unroll
    for (int j = 0; j < 8; ++j) {
        int cur = j & 1, nxt = cur ^ 1;
        if (j < 7) {
            int coln = 64 * (j + 1) + colb;
            #pragma unroll
            for (int nf = 0; nf < 2; ++nf) {
                cb[nxt][0][nf] = __ldg((const float2*)(Cp + (size_t)r0 * SDIM + coln + 8 * nf));
                cb[nxt][1][nf] = __ldg((const float2*)(Cp + (size_t)r1 * SDIM + coln + 8 * nf));
            }
        }
        uint32_t wah[4], wal[4];
        #pragma unroll
        for (int nf = 0; nf < 2; ++nf) {
            int col = 64 * j + colb + 8 * nf;
            float p00 = sc[j][nf][0] * inv0, p01 = sc[j][nf][1] * inv0;
            float p10 = sc[j][nf][2] * inv1, p11 = sc[j][nf][3] * inv1;
            __stcs((float2*)(Pp + (size_t)r0 * SDIM + col), make_float2(p00, p01));
            __stcs((float2*)(Pp + (size_t)r1 * SDIM + col), make_float2(p10, p11));
            float w00 = fmaf(L_ATT, p00, cb[cur][0][nf].x);
            float w01 = fmaf(L_ATT, p01, cb[cur][0][nf].y);
            float w10 = fmaf(L_ATT, p10, cb[cur][1][nf].x);
            float w11 = fmaf(L_ATT, p11, cb[cur][1][nf].y);
            wah[2 * nf]     = packbf(w00, w01);
            wah[2 * nf + 1] = packbf(w10, w11);
            wal[2 * nf]     = packbf(w00 - bfround(w00), w01 - bfround(w01));
            wal[2 * nf + 1] = packbf(w10 - bfround(w10), w11 - bfround(w11));
        }

        uint32_t vrow = sb + OFF_V + (64 * j + 16 * wn + lr8 + 8 * lg) * KSTRB + 73728 * kg4;
        uint32_t vb[2][4];
        ldm_x4t(vb[0], vrow);
        #pragma unroll
        for (int nj = 0; nj < 8; ++nj) {
            int vc = nj & 1;
            if (nj < 7) ldm_x4t(vb[vc ^ 1], vrow + 16 * (nj + 1));
            mma_bf16(accO[nj], wah, vb[vc]);
            mma_bf16(accO[nj], wal, vb[vc]);
            mma_bf16(accO[nj], wah, vb[vc] + 2);
        }
    }

    // ---- reduce 4 wn partials ----
    #pragma unroll
    for (int r = 0; r < 4; ++r) {
        __syncthreads();
        if (wn == r) {
            #pragma unroll
            for (int nj = 0; nj < 8; ++nj) {
                int col = 8 * nj + 2 * lc;
                float2* p0 = (float2*)(sRed + r0 * RSTR + col);
                float2* p1 = (float2*)(sRed + r1 * RSTR + col);
                if (r == 0) {
                    *p0 = make_float2(accO[nj][0], accO[nj][1]);
                    *p1 = make_float2(accO[nj][2], accO[nj][3]);
                } else {
                    float2 a = *p0, bq = *p1;
                    a.x += accO[nj][0]; a.y += accO[nj][1];
                    bq.x += accO[nj][2]; bq.y += accO[nj][3];
                    *p0 = a; *p1 = bq;
                }
            }
        }
    }
    __syncthreads();

    #pragma unroll
    for (int t = 0; t < 2; ++t) {
        int idx = tid + 512 * t;
        int row = idx >> 4, c0 = (idx & 15) << 2;
        *(float4*)(Op + row * DDIM + c0) = *(float4*)(sRed + row * RSTR + c0);
    }
}

extern "C" void kernel_launch(void* const* d_in, const int* in_sizes, int n_in,
                              void* d_out, int out_size)
{
    const float* Q    = (const float*)d_in[0];
    const float* K    = (const float*)d_in[1];
    const float* V    = (const float*)d_in[2];
    const float* mask = (const float*)d_in[3];
    const float* adj  = (const float*)d_in[4];
    const float* dist = (const float*)d_in[5];

    float* outp  = (float*)d_out;
    float* pattn = outp + (size_t)BB * HH * SDIM * DDIM;

    precompute_C_kernel<<<BB * SDIM, 256>>>(adj, dist, mask);

    cudaFuncSetAttribute(attn_mma_kernel,
                         cudaFuncAttributeMaxDynamicSharedMemorySize, SMEM_BYTES);
    dim3 grid(SDIM / QT, HH, BB);
    attn_mma_kernel<<<grid, THREADS, SMEM_BYTES>>>(Q, K, V, mask, outp, pattn);
}